// round 8
// baseline (speedup 1.0000x reference)
#include <cuda_runtime.h>
#include <cuda_bf16.h>
#include <math.h>
#include <stdint.h>

// Problem dims
#define BB 2
#define SS 2048
#define EE 2048
#define HH 16
#define KVH 4
#define HD 128
#define ROWS (BB * SS)    // 4096
#define NKV (KVH * HD)    // 512
#define NC (EE + 2 * NKV) // 3072

// ---------------------------------------------------------------------------
// Scratch (__device__ globals; no cudaMalloc allowed)
// ---------------------------------------------------------------------------
__device__ __nv_bfloat16 g_Xh[(size_t)ROWS * EE];
__device__ __nv_bfloat16 g_Xl[(size_t)ROWS * EE];
__device__ __nv_bfloat16 g_Qbh[(size_t)ROWS * EE];
__device__ __nv_bfloat16 g_Qbl[(size_t)ROWS * EE];
__device__ __nv_bfloat16 g_Kbh[(size_t)ROWS * NKV];
__device__ __nv_bfloat16 g_Kbl[(size_t)ROWS * NKV];
__device__ __nv_bfloat16 g_Vbh[(size_t)ROWS * NKV];
__device__ __nv_bfloat16 g_Vbl[(size_t)ROWS * NKV];
__device__ __nv_bfloat16 g_CXh[(size_t)ROWS * EE];
__device__ __nv_bfloat16 g_CXl[(size_t)ROWS * EE];
__device__ __nv_bfloat16 g_Wch[(size_t)NC * EE];
__device__ __nv_bfloat16 g_Wcl[(size_t)NC * EE];
__device__ __nv_bfloat16 g_Woh[(size_t)EE * EE];
__device__ __nv_bfloat16 g_Wol[(size_t)EE * EE];

// ---------------------------------------------------------------------------
// MMA / cp.async helpers
// ---------------------------------------------------------------------------
__device__ __forceinline__ uint32_t smem_u32(const void* p) {
    uint32_t a;
    asm("{ .reg .u64 t; cvta.to.shared.u64 t, %1; cvt.u32.u64 %0, t; }"
        : "=r"(a) : "l"(p));
    return a;
}
__device__ __forceinline__ void ldsm_x4(uint32_t* r, uint32_t addr) {
    asm volatile("ldmatrix.sync.aligned.m8n8.x4.shared.b16 {%0,%1,%2,%3}, [%4];"
                 : "=r"(r[0]), "=r"(r[1]), "=r"(r[2]), "=r"(r[3]) : "r"(addr));
}
__device__ __forceinline__ void ldsm_x4_t(uint32_t* r, uint32_t addr) {
    asm volatile("ldmatrix.sync.aligned.m8n8.x4.trans.shared.b16 {%0,%1,%2,%3}, [%4];"
                 : "=r"(r[0]), "=r"(r[1]), "=r"(r[2]), "=r"(r[3]) : "r"(addr));
}
__device__ __forceinline__ void mma16816(float* c, const uint32_t* a,
                                         uint32_t b0, uint32_t b1) {
    asm volatile(
        "mma.sync.aligned.m16n8k16.row.col.f32.bf16.bf16.f32 "
        "{%0,%1,%2,%3}, {%4,%5,%6,%7}, {%8,%9}, {%0,%1,%2,%3};"
        : "+f"(c[0]), "+f"(c[1]), "+f"(c[2]), "+f"(c[3])
        : "r"(a[0]), "r"(a[1]), "r"(a[2]), "r"(a[3]), "r"(b0), "r"(b1));
}
__device__ __forceinline__ void cp16(uint32_t dst, const void* src) {
    asm volatile("cp.async.cg.shared.global [%0], [%1], 16;" :: "r"(dst), "l"(src));
}
__device__ __forceinline__ void cp_commit() {
    asm volatile("cp.async.commit_group;" ::: "memory");
}
template <int N> __device__ __forceinline__ void cp_wait() {
    asm volatile("cp.async.wait_group %0;" :: "n"(N) : "memory");
}
__device__ __forceinline__ uint32_t pack_bf16(__nv_bfloat16 a, __nv_bfloat16 b) {
    __nv_bfloat162 t(a, b);
    return *(uint32_t*)&t;
}
// split-write a fp32 pair to hi/lo bf16 buffers (offset must be even)
__device__ __forceinline__ void wsplit(__nv_bfloat16* __restrict__ H,
                                       __nv_bfloat16* __restrict__ L,
                                       size_t o, float a, float b) {
    __nv_bfloat16 h0 = __float2bfloat16(a), h1 = __float2bfloat16(b);
    *(uint32_t*)(H + o) = pack_bf16(h0, h1);
    *(uint32_t*)(L + o) =
        pack_bf16(__float2bfloat16(a - __bfloat162float(h0)),
                  __float2bfloat16(b - __bfloat162float(h1)));
}

// ---------------------------------------------------------------------------
// fp32 -> (hi, lo) bf16 split, elementwise (vectorized x4)
// ---------------------------------------------------------------------------
__global__ __launch_bounds__(256) void split_kernel(const float* __restrict__ in,
                                                    __nv_bfloat16* __restrict__ hi,
                                                    __nv_bfloat16* __restrict__ lo,
                                                    int n4) {
    int i = blockIdx.x * blockDim.x + threadIdx.x;
    if (i >= n4) return;
    float4 v = ((const float4*)in)[i];
    __nv_bfloat16 h0 = __float2bfloat16(v.x), h1 = __float2bfloat16(v.y);
    __nv_bfloat16 h2 = __float2bfloat16(v.z), h3 = __float2bfloat16(v.w);
    __nv_bfloat16 l0 = __float2bfloat16(v.x - __bfloat162float(h0));
    __nv_bfloat16 l1 = __float2bfloat16(v.y - __bfloat162float(h1));
    __nv_bfloat16 l2 = __float2bfloat16(v.z - __bfloat162float(h2));
    __nv_bfloat16 l3 = __float2bfloat16(v.w - __bfloat162float(h3));
    ((__nv_bfloat162*)hi)[i * 2 + 0] = __nv_bfloat162(h0, h1);
    ((__nv_bfloat162*)hi)[i * 2 + 1] = __nv_bfloat162(h2, h3);
    ((__nv_bfloat162*)lo)[i * 2 + 0] = __nv_bfloat162(l0, l1);
    ((__nv_bfloat162*)lo)[i * 2 + 1] = __nv_bfloat162(l2, l3);
}

// ---------------------------------------------------------------------------
// Transpose + split: in fp32 [Kd, Nd] -> out bf16 [Nd, Kd] (hi, lo)
// ---------------------------------------------------------------------------
__global__ __launch_bounds__(256) void tsplit_kernel(const float* __restrict__ in,
                                                     __nv_bfloat16* __restrict__ oh,
                                                     __nv_bfloat16* __restrict__ ol,
                                                     int Kd, int Nd) {
    __shared__ float t[32][33];
    int n0 = blockIdx.x * 32, k0 = blockIdx.y * 32;
    int tx = threadIdx.x & 31, ty = threadIdx.x >> 5;
#pragma unroll
    for (int j = 0; j < 4; j++)
        t[ty + j * 8][tx] = in[(size_t)(k0 + ty + j * 8) * Nd + n0 + tx];
    __syncthreads();
#pragma unroll
    for (int j = 0; j < 4; j++) {
        float v = t[tx][ty + j * 8];
        __nv_bfloat16 h = __float2bfloat16(v);
        __nv_bfloat16 l = __float2bfloat16(v - __bfloat162float(h));
        size_t o = (size_t)(n0 + ty + j * 8) * Kd + k0 + tx;
        oh[o] = h;
        ol[o] = l;
    }
}

// ---------------------------------------------------------------------------
// HMMA bf16 split-precision GEMM, 3-stage cp.async pipeline, 1 sync/iter.
// mode 0: plain fp32 C write. mode 1: fused QKV epilogue (RoPE+scale+split).
// ---------------------------------------------------------------------------
#define GROW 40
#define GARR (128 * GROW * 2)
#define GSTAGE_B (4 * GARR)          // 40960
#define GEMM_SMEM (3 * GSTAGE_B)     // 122880

#define GLOAD(kc, st)                                                        \
    do {                                                                     \
        uint32_t uS = uBase + (st) * GSTAGE_B;                               \
        int koff = (kc) * 32;                                                \
        _Pragma("unroll") for (int t = 0; t < 2; t++) {                      \
            int idx = tid + t * 256;                                         \
            int r = idx >> 2, c8 = (idx & 3) * 8;                            \
            size_t go = (size_t)r * K + koff + c8;                           \
            uint32_t dso = (uint32_t)(r * (GROW * 2) + c8 * 2);              \
            cp16(uS + dso, gAh + go);                                        \
            cp16(uS + GARR + dso, gAl + go);                                 \
            cp16(uS + 2 * GARR + dso, gBh + go);                             \
            cp16(uS + 3 * GARR + dso, gBl + go);                             \
        }                                                                    \
    } while (0)

__global__ __launch_bounds__(256) void gemm_mma(
    const __nv_bfloat16* __restrict__ Ah, const __nv_bfloat16* __restrict__ Al,
    const __nv_bfloat16* __restrict__ Bh, const __nv_bfloat16* __restrict__ Bl,
    float* __restrict__ Cf,
    __nv_bfloat16* __restrict__ Qh, __nv_bfloat16* __restrict__ Ql,
    __nv_bfloat16* __restrict__ Kh2, __nv_bfloat16* __restrict__ Kl2,
    __nv_bfloat16* __restrict__ Vh2, __nv_bfloat16* __restrict__ Vl2,
    int mode, int M, int N, int K) {
    extern __shared__ char gsm[];
    const uint32_t uBase = smem_u32(gsm);

    const int tid = threadIdx.x, wid = tid >> 5, lane = tid & 31;
    const int m0 = blockIdx.y * 128, n0 = blockIdx.x * 128;
    const int warp_m = (wid >> 2) * 64;
    const int warp_n = (wid & 3) * 32;

    const int a_roff = ((lane >> 3) & 1) * 8 + (lane & 7);
    const int a_coff = (lane >> 4) * 8;
    const int b_roff = (lane >> 4) * 8 + (lane & 7);
    const int b_coff = ((lane >> 3) & 1) * 8;

    float acc[4][4][4];
#pragma unroll
    for (int i = 0; i < 4; i++)
#pragma unroll
        for (int j = 0; j < 4; j++)
#pragma unroll
            for (int c = 0; c < 4; c++) acc[i][j][c] = 0.f;

    const __nv_bfloat16* gAh = Ah + (size_t)m0 * K;
    const __nv_bfloat16* gAl = Al + (size_t)m0 * K;
    const __nv_bfloat16* gBh = Bh + (size_t)n0 * K;
    const __nv_bfloat16* gBl = Bl + (size_t)n0 * K;

    const int KC = K >> 5;
    GLOAD(0, 0);
    cp_commit();
    GLOAD(1, 1);
    cp_commit();

    int st = 0;         // stage of current compute tile
    int stp = 2;        // stage for next prefetch
    for (int kc = 0; kc < KC; kc++) {
        if (kc + 1 < KC) cp_wait<1>(); else cp_wait<0>();
        __syncthreads();
        if (kc + 2 < KC) {
            GLOAD(kc + 2, stp);
            cp_commit();
        }

        const uint32_t uS = uBase + st * GSTAGE_B;
        const uint32_t uAh = uS, uAl = uS + GARR;
        const uint32_t uBh = uS + 2 * GARR, uBl = uS + 3 * GARR;

#pragma unroll
        for (int ks = 0; ks < 2; ks++) {
            uint32_t ah[4][4], al[4][4], bh[2][4], bl[2][4];
#pragma unroll
            for (int mt = 0; mt < 4; mt++) {
                uint32_t off =
                    (uint32_t)((warp_m + mt * 16 + a_roff) * GROW +
                               ks * 16 + a_coff) * 2;
                ldsm_x4(ah[mt], uAh + off);
                ldsm_x4(al[mt], uAl + off);
            }
#pragma unroll
            for (int p = 0; p < 2; p++) {
                uint32_t off =
                    (uint32_t)((warp_n + p * 16 + b_roff) * GROW +
                               ks * 16 + b_coff) * 2;
                ldsm_x4(bh[p], uBh + off);
                ldsm_x4(bl[p], uBl + off);
            }
#pragma unroll
            for (int mt = 0; mt < 4; mt++) {
#pragma unroll
                for (int p = 0; p < 2; p++) {
#pragma unroll
                    for (int hf = 0; hf < 2; hf++) {
                        float* c = acc[mt][p * 2 + hf];
                        uint32_t b0h = bh[p][hf * 2], b1h = bh[p][hf * 2 + 1];
                        uint32_t b0l = bl[p][hf * 2], b1l = bl[p][hf * 2 + 1];
                        mma16816(c, ah[mt], b0h, b1h);
                        mma16816(c, ah[mt], b0l, b1l);
                        mma16816(c, al[mt], b0h, b1h);
                    }
                }
            }
        }
        st = (st == 2) ? 0 : st + 1;
        stp = (stp == 2) ? 0 : stp + 1;
    }

    const int cr = lane >> 2, cc = (lane & 3) * 2;
    if (mode == 0) {
#pragma unroll
        for (int mt = 0; mt < 4; mt++) {
#pragma unroll
            for (int nt = 0; nt < 4; nt++) {
                int row = m0 + warp_m + mt * 16 + cr;
                int col = n0 + warp_n + nt * 8 + cc;
                float* c = acc[mt][nt];
                *(float2*)(Cf + (size_t)row * N + col) = make_float2(c[0], c[1]);
                *(float2*)(Cf + (size_t)(row + 8) * N + col) =
                    make_float2(c[2], c[3]);
            }
        }
    } else {
        // QKV fused epilogue: col pair (col, col+1) is a RoPE rotation pair
        const float qscale = 0.08838834764831845f;  // 1/sqrt(HD)
#pragma unroll
        for (int mt = 0; mt < 4; mt++) {
#pragma unroll
            for (int nt = 0; nt < 4; nt++) {
                int row = m0 + warp_m + mt * 16 + cr;
                int col = n0 + warp_n + nt * 8 + cc;
                float* c = acc[mt][nt];
                int s0 = row & (SS - 1);
                if (col < EE) {
                    int i = (col & (HD - 1)) >> 1;
                    float f = exp2f(-(float)i * (13.287712379549449f / 64.0f));
                    float sn0, cs0, sn1, cs1;
                    sincosf((float)s0 * f, &sn0, &cs0);
                    sincosf((float)(s0 + 8) * f, &sn1, &cs1);
                    wsplit(Qh, Ql, (size_t)row * EE + col,
                           (c[0] * cs0 - c[1] * sn0) * qscale,
                           (c[0] * sn0 + c[1] * cs0) * qscale);
                    wsplit(Qh, Ql, (size_t)(row + 8) * EE + col,
                           (c[2] * cs1 - c[3] * sn1) * qscale,
                           (c[2] * sn1 + c[3] * cs1) * qscale);
                } else if (col < EE + NKV) {
                    int colk = col - EE;
                    int i = (colk & (HD - 1)) >> 1;
                    float f = exp2f(-(float)i * (13.287712379549449f / 64.0f));
                    float sn0, cs0, sn1, cs1;
                    sincosf((float)s0 * f, &sn0, &cs0);
                    sincosf((float)(s0 + 8) * f, &sn1, &cs1);
                    wsplit(Kh2, Kl2, (size_t)row * NKV + colk,
                           c[0] * cs0 - c[1] * sn0, c[0] * sn0 + c[1] * cs0);
                    wsplit(Kh2, Kl2, (size_t)(row + 8) * NKV + colk,
                           c[2] * cs1 - c[3] * sn1, c[2] * sn1 + c[3] * cs1);
                } else {
                    int colv = col - EE - NKV;
                    wsplit(Vh2, Vl2, (size_t)row * NKV + colv, c[0], c[1]);
                    wsplit(Vh2, Vl2, (size_t)(row + 8) * NKV + colv, c[2], c[3]);
                }
            }
        }
    }
}

// ---------------------------------------------------------------------------
// Flash attention on HMMA (causal, GQA, 3-pass hi/lo split)
// BQ=128 (8 warps x 16 rows), BK=64, HD=128. P in registers.
// Epilogue writes bf16 hi/lo context directly (fused split).
// ---------------------------------------------------------------------------
#define FROW 136
#define FQ_B (128 * FROW * 2)
#define FKV_B (64 * FROW * 2)
#define FSTAGE_B (4 * FKV_B)
#define FLA_SMEM (2 * FQ_B + 2 * FSTAGE_B)   // 208896

#define KVLOAD(j, st)                                                         \
    do {                                                                      \
        uint32_t uS = uBase + 2 * FQ_B + (st) * FSTAGE_B;                     \
        _Pragma("unroll") for (int t = 0; t < 4; t++) {                       \
            int i = tid + t * 256;                                            \
            int r = i >> 4, c8 = (i & 15) << 3;                               \
            size_t g = (size_t)(b * SS + (j) * 64 + r) * NKV + kvh * HD + c8; \
            uint32_t dso = (uint32_t)(r * (FROW * 2) + c8 * 2);               \
            cp16(uS + dso, Kh + g);                                           \
            cp16(uS + FKV_B + dso, Kl + g);                                   \
            cp16(uS + 2 * FKV_B + dso, Vh + g);                               \
            cp16(uS + 3 * FKV_B + dso, Vl + g);                               \
        }                                                                     \
    } while (0)

__global__ __launch_bounds__(256) void flash_mma(
    const __nv_bfloat16* __restrict__ Qh, const __nv_bfloat16* __restrict__ Ql,
    const __nv_bfloat16* __restrict__ Kh, const __nv_bfloat16* __restrict__ Kl,
    const __nv_bfloat16* __restrict__ Vh, const __nv_bfloat16* __restrict__ Vl,
    __nv_bfloat16* __restrict__ Oh, __nv_bfloat16* __restrict__ Ol) {
    extern __shared__ char fsm[];
    const uint32_t uBase = smem_u32(fsm);
    const uint32_t uQh = uBase, uQl = uBase + FQ_B;

    const int qt = gridDim.x - 1 - blockIdx.x;   // heavy tiles first
    const int h = blockIdx.y, b = blockIdx.z;
    const int kvh = h >> 2;
    const int tid = threadIdx.x, wid = tid >> 5, lane = tid & 31;
    const int cr = lane >> 2, tc = (lane & 3) << 1;

    const int a_roff = ((lane >> 3) & 1) * 8 + (lane & 7);
    const int a_coff = (lane >> 4) * 8;
    const int b_roff = (lane >> 4) * 8 + (lane & 7);
    const int b_coff = ((lane >> 3) & 1) * 8;
    const int v_roff = ((lane >> 3) & 1) * 8 + (lane & 7);
    const int v_coff = (lane >> 4) * 8;

    {
        const size_t qbase = (size_t)(b * SS + qt * 128) * EE + h * HD;
#pragma unroll
        for (int t = 0; t < 8; t++) {
            int i = tid + t * 256;
            int r = i >> 4, c8 = (i & 15) << 3;
            size_t g = qbase + (size_t)r * EE + c8;
            uint32_t dso = (uint32_t)(r * (FROW * 2) + c8 * 2);
            cp16(uQh + dso, Qh + g);
            cp16(uQl + dso, Ql + g);
        }
        cp_commit();
    }
    KVLOAD(0, 0);
    cp_commit();

    uint32_t qh[8][4];
    float oacc[16][4];
#pragma unroll
    for (int i = 0; i < 16; i++)
#pragma unroll
        for (int c = 0; c < 4; c++) oacc[i][c] = 0.f;
    float m0 = -1e30f, m1 = -1e30f, l0 = 0.f, l1 = 0.f;

    const int border = qt * 128 + wid * 16;
    const int jmax = 2 * qt + 1;

    for (int j = 0; j <= jmax; j++) {
        if (j + 1 <= jmax) {
            KVLOAD(j + 1, (j + 1) & 1);
            cp_commit();
            cp_wait<1>();
        } else {
            cp_wait<0>();
        }
        __syncthreads();

        if (j == 0) {
#pragma unroll
            for (int ks = 0; ks < 8; ks++)
                ldsm_x4(qh[ks],
                        uQh + (uint32_t)((wid * 16 + a_roff) * FROW +
                                         ks * 16 + a_coff) * 2);
        }

        const uint32_t uS = uBase + 2 * FQ_B + (j & 1) * FSTAGE_B;
        const uint32_t uKh = uS, uKl = uS + FKV_B;
        const uint32_t uVh = uS + 2 * FKV_B, uVl = uS + 3 * FKV_B;

        if (j * 64 <= border + 15) {
            float sacc[8][4];
#pragma unroll
            for (int nt = 0; nt < 8; nt++)
#pragma unroll
                for (int c = 0; c < 4; c++) sacc[nt][c] = 0.f;

#pragma unroll
            for (int ks = 0; ks < 8; ks++) {
                uint32_t kh4[4][4], kl4[4][4], qlf[4];
#pragma unroll
                for (int p = 0; p < 4; p++) {
                    uint32_t off =
                        (uint32_t)((p * 16 + b_roff) * FROW +
                                   ks * 16 + b_coff) * 2;
                    ldsm_x4(kh4[p], uKh + off);
                    ldsm_x4(kl4[p], uKl + off);
                }
                ldsm_x4(qlf, uQl + (uint32_t)((wid * 16 + a_roff) * FROW +
                                              ks * 16 + a_coff) * 2);
#pragma unroll
                for (int p = 0; p < 4; p++)
#pragma unroll
                    for (int hf = 0; hf < 2; hf++) {
                        float* c = sacc[p * 2 + hf];
                        mma16816(c, qh[ks], kh4[p][hf * 2], kh4[p][hf * 2 + 1]);
                        mma16816(c, qh[ks], kl4[p][hf * 2], kl4[p][hf * 2 + 1]);
                        mma16816(c, qlf,    kh4[p][hf * 2], kh4[p][hf * 2 + 1]);
                    }
            }

            if (j * 64 + 63 > border) {
                int qg0 = border + cr, qg1 = qg0 + 8;
#pragma unroll
                for (int nt = 0; nt < 8; nt++) {
                    int kg = j * 64 + nt * 8 + tc;
                    if (kg > qg0) sacc[nt][0] = -1e30f;
                    if (kg + 1 > qg0) sacc[nt][1] = -1e30f;
                    if (kg > qg1) sacc[nt][2] = -1e30f;
                    if (kg + 1 > qg1) sacc[nt][3] = -1e30f;
                }
            }

            float mx0 = -1e30f, mx1 = -1e30f;
#pragma unroll
            for (int nt = 0; nt < 8; nt++) {
                mx0 = fmaxf(mx0, fmaxf(sacc[nt][0], sacc[nt][1]));
                mx1 = fmaxf(mx1, fmaxf(sacc[nt][2], sacc[nt][3]));
            }
            mx0 = fmaxf(mx0, __shfl_xor_sync(0xffffffffu, mx0, 1, 4));
            mx0 = fmaxf(mx0, __shfl_xor_sync(0xffffffffu, mx0, 2, 4));
            mx1 = fmaxf(mx1, __shfl_xor_sync(0xffffffffu, mx1, 1, 4));
            mx1 = fmaxf(mx1, __shfl_xor_sync(0xffffffffu, mx1, 2, 4));
            float mn0 = fmaxf(m0, mx0), mn1 = fmaxf(m1, mx1);
            float al0 = __expf(m0 - mn0), al1 = __expf(m1 - mn1);

            float sum0 = 0.f, sum1 = 0.f;
            uint32_t ph[8][2], pl[8][2];
#pragma unroll
            for (int nt = 0; nt < 8; nt++) {
                float p00 = __expf(sacc[nt][0] - mn0);
                float p01 = __expf(sacc[nt][1] - mn0);
                float p10 = __expf(sacc[nt][2] - mn1);
                float p11 = __expf(sacc[nt][3] - mn1);
                sum0 += p00 + p01;
                sum1 += p10 + p11;
                __nv_bfloat16 h0 = __float2bfloat16(p00), h1 = __float2bfloat16(p01);
                __nv_bfloat16 h2 = __float2bfloat16(p10), h3 = __float2bfloat16(p11);
                ph[nt][0] = pack_bf16(h0, h1);
                ph[nt][1] = pack_bf16(h2, h3);
                pl[nt][0] = pack_bf16(__float2bfloat16(p00 - __bfloat162float(h0)),
                                      __float2bfloat16(p01 - __bfloat162float(h1)));
                pl[nt][1] = pack_bf16(__float2bfloat16(p10 - __bfloat162float(h2)),
                                      __float2bfloat16(p11 - __bfloat162float(h3)));
            }
            sum0 += __shfl_xor_sync(0xffffffffu, sum0, 1, 4);
            sum0 += __shfl_xor_sync(0xffffffffu, sum0, 2, 4);
            sum1 += __shfl_xor_sync(0xffffffffu, sum1, 1, 4);
            sum1 += __shfl_xor_sync(0xffffffffu, sum1, 2, 4);
            l0 = l0 * al0 + sum0;
            l1 = l1 * al1 + sum1;
            m0 = mn0;
            m1 = mn1;
#pragma unroll
            for (int nt = 0; nt < 16; nt++) {
                oacc[nt][0] *= al0;
                oacc[nt][1] *= al0;
                oacc[nt][2] *= al1;
                oacc[nt][3] *= al1;
            }

#pragma unroll
            for (int ks = 0; ks < 4; ks++) {
                uint32_t ah4[4] = {ph[2 * ks][0], ph[2 * ks][1],
                                   ph[2 * ks + 1][0], ph[2 * ks + 1][1]};
                uint32_t alo[4] = {pl[2 * ks][0], pl[2 * ks][1],
                                   pl[2 * ks + 1][0], pl[2 * ks + 1][1]};
#pragma unroll
                for (int p = 0; p < 8; p++) {
                    uint32_t vh4[4], vl4[4];
                    uint32_t off =
                        (uint32_t)((ks * 16 + v_roff) * FROW +
                                   p * 16 + v_coff) * 2;
                    ldsm_x4_t(vh4, uVh + off);
                    ldsm_x4_t(vl4, uVl + off);
#pragma unroll
                    for (int hf = 0; hf < 2; hf++) {
                        float* c = oacc[p * 2 + hf];
                        mma16816(c, ah4, vh4[hf * 2], vh4[hf * 2 + 1]);
                        mma16816(c, ah4, vl4[hf * 2], vl4[hf * 2 + 1]);
                        mma16816(c, alo, vh4[hf * 2], vh4[hf * 2 + 1]);
                    }
                }
            }
        }
        __syncthreads();
    }

    // ---- Epilogue: normalize + split to bf16 hi/lo context ----
    float inv0 = 1.0f / l0, inv1 = 1.0f / l1;
    int row0 = qt * 128 + wid * 16 + cr;
    size_t obase = (size_t)(b * SS + row0) * EE + h * HD;
#pragma unroll
    for (int nt = 0; nt < 16; nt++) {
        int col = nt * 8 + tc;
        wsplit(Oh, Ol, obase + col, oacc[nt][0] * inv0, oacc[nt][1] * inv0);
        wsplit(Oh, Ol, obase + (size_t)8 * EE + col,
               oacc[nt][2] * inv1, oacc[nt][3] * inv1);
    }
}

// ---------------------------------------------------------------------------
// Launch
// ---------------------------------------------------------------------------
extern "C" void kernel_launch(void* const* d_in, const int* in_sizes, int n_in,
                              void* d_out, int out_size) {
    const float* x  = (const float*)d_in[0];
    const float* Wq = (const float*)d_in[1];
    const float* Wk = (const float*)d_in[2];
    const float* Wv = (const float*)d_in[3];
    const float* Wo = (const float*)d_in[4];

    __nv_bfloat16 *Xh, *Xl, *Qbh, *Qbl, *Kbh, *Kbl, *Vbh, *Vbl, *CXh, *CXl,
        *Wch, *Wcl, *Woh, *Wol;
    cudaGetSymbolAddress((void**)&Xh, g_Xh);
    cudaGetSymbolAddress((void**)&Xl, g_Xl);
    cudaGetSymbolAddress((void**)&Qbh, g_Qbh);
    cudaGetSymbolAddress((void**)&Qbl, g_Qbl);
    cudaGetSymbolAddress((void**)&Kbh, g_Kbh);
    cudaGetSymbolAddress((void**)&Kbl, g_Kbl);
    cudaGetSymbolAddress((void**)&Vbh, g_Vbh);
    cudaGetSymbolAddress((void**)&Vbl, g_Vbl);
    cudaGetSymbolAddress((void**)&CXh, g_CXh);
    cudaGetSymbolAddress((void**)&CXl, g_CXl);
    cudaGetSymbolAddress((void**)&Wch, g_Wch);
    cudaGetSymbolAddress((void**)&Wcl, g_Wcl);
    cudaGetSymbolAddress((void**)&Woh, g_Woh);
    cudaGetSymbolAddress((void**)&Wol, g_Wol);

    cudaFuncSetAttribute(gemm_mma, cudaFuncAttributeMaxDynamicSharedMemorySize,
                         GEMM_SMEM);
    cudaFuncSetAttribute(flash_mma, cudaFuncAttributeMaxDynamicSharedMemorySize,
                         FLA_SMEM);

    // Split x; transpose+split weights (QKV concat + Wo)
    split_kernel<<<(ROWS * EE / 4 + 255) / 256, 256>>>(x, Xh, Xl, ROWS * EE / 4);
    tsplit_kernel<<<dim3(EE / 32, EE / 32), 256>>>(Wq, Wch, Wcl, EE, EE);
    tsplit_kernel<<<dim3(NKV / 32, EE / 32), 256>>>(
        Wk, Wch + (size_t)EE * EE, Wcl + (size_t)EE * EE, EE, NKV);
    tsplit_kernel<<<dim3(NKV / 32, EE / 32), 256>>>(
        Wv, Wch + (size_t)(EE + NKV) * EE, Wcl + (size_t)(EE + NKV) * EE, EE, NKV);
    tsplit_kernel<<<dim3(EE / 32, EE / 32), 256>>>(Wo, Woh, Wol, EE, EE);

    // Fused QKV projection with RoPE+split epilogue
    gemm_mma<<<dim3(NC / 128, ROWS / 128), 256, GEMM_SMEM>>>(
        Xh, Xl, Wch, Wcl, nullptr, Qbh, Qbl, Kbh, Kbl, Vbh, Vbl,
        1, ROWS, NC, EE);

    // Flash attention (epilogue writes bf16 hi/lo context)
    flash_mma<<<dim3(SS / 128, HH, BB), 256, FLA_SMEM>>>(
        Qbh, Qbl, Kbh, Kbl, Vbh, Vbl, CXh, CXl);

    // Output projection -> d_out (fp32)
    gemm_mma<<<dim3(EE / 128, ROWS / 128), 256, GEMM_SMEM>>>(
        CXh, CXl, Woh, Wol, (float*)d_out, nullptr, nullptr, nullptr, nullptr,
        nullptr, nullptr, 0, ROWS, EE, EE);
}

// round 9
// speedup vs baseline: 1.1797x; 1.1797x over previous
#include <cuda_runtime.h>
#include <cuda_bf16.h>
#include <math.h>
#include <stdint.h>

// Problem dims
#define BB 2
#define SS 2048
#define EE 2048
#define HH 16
#define KVH 4
#define HD 128
#define ROWS (BB * SS)    // 4096
#define NKV (KVH * HD)    // 512
#define NC (EE + 2 * NKV) // 3072

// ---------------------------------------------------------------------------
// Scratch (__device__ globals; no cudaMalloc allowed)
// ---------------------------------------------------------------------------
__device__ __nv_bfloat16 g_Xh[(size_t)ROWS * EE];
__device__ __nv_bfloat16 g_Xl[(size_t)ROWS * EE];
__device__ __nv_bfloat16 g_Qbh[(size_t)ROWS * EE];
__device__ __nv_bfloat16 g_Qbl[(size_t)ROWS * EE];
__device__ __nv_bfloat16 g_Kbh[(size_t)ROWS * NKV];
__device__ __nv_bfloat16 g_Kbl[(size_t)ROWS * NKV];
__device__ __nv_bfloat16 g_Vbh[(size_t)ROWS * NKV];
__device__ __nv_bfloat16 g_Vbl[(size_t)ROWS * NKV];
__device__ __nv_bfloat16 g_CXh[(size_t)ROWS * EE];
__device__ __nv_bfloat16 g_CXl[(size_t)ROWS * EE];
__device__ __nv_bfloat16 g_Wch[(size_t)NC * EE];
__device__ __nv_bfloat16 g_Wcl[(size_t)NC * EE];
__device__ __nv_bfloat16 g_Woh[(size_t)EE * EE];
__device__ __nv_bfloat16 g_Wol[(size_t)EE * EE];

// ---------------------------------------------------------------------------
// MMA / cp.async helpers
// ---------------------------------------------------------------------------
__device__ __forceinline__ uint32_t smem_u32(const void* p) {
    uint32_t a;
    asm("{ .reg .u64 t; cvta.to.shared.u64 t, %1; cvt.u32.u64 %0, t; }"
        : "=r"(a) : "l"(p));
    return a;
}
__device__ __forceinline__ void ldsm_x4(uint32_t* r, uint32_t addr) {
    asm volatile("ldmatrix.sync.aligned.m8n8.x4.shared.b16 {%0,%1,%2,%3}, [%4];"
                 : "=r"(r[0]), "=r"(r[1]), "=r"(r[2]), "=r"(r[3]) : "r"(addr));
}
__device__ __forceinline__ void ldsm_x4_t(uint32_t* r, uint32_t addr) {
    asm volatile("ldmatrix.sync.aligned.m8n8.x4.trans.shared.b16 {%0,%1,%2,%3}, [%4];"
                 : "=r"(r[0]), "=r"(r[1]), "=r"(r[2]), "=r"(r[3]) : "r"(addr));
}
__device__ __forceinline__ void mma16816(float* c, const uint32_t* a,
                                         uint32_t b0, uint32_t b1) {
    asm volatile(
        "mma.sync.aligned.m16n8k16.row.col.f32.bf16.bf16.f32 "
        "{%0,%1,%2,%3}, {%4,%5,%6,%7}, {%8,%9}, {%0,%1,%2,%3};"
        : "+f"(c[0]), "+f"(c[1]), "+f"(c[2]), "+f"(c[3])
        : "r"(a[0]), "r"(a[1]), "r"(a[2]), "r"(a[3]), "r"(b0), "r"(b1));
}
__device__ __forceinline__ void cp16(uint32_t dst, const void* src) {
    asm volatile("cp.async.cg.shared.global [%0], [%1], 16;" :: "r"(dst), "l"(src));
}
__device__ __forceinline__ void cp_commit() {
    asm volatile("cp.async.commit_group;" ::: "memory");
}
template <int N> __device__ __forceinline__ void cp_wait() {
    asm volatile("cp.async.wait_group %0;" :: "n"(N) : "memory");
}
__device__ __forceinline__ float fex2(float x) {
    float r;
    asm("ex2.approx.f32 %0, %1;" : "=f"(r) : "f"(x));
    return r;
}
__device__ __forceinline__ uint32_t pack_bf16(__nv_bfloat16 a, __nv_bfloat16 b) {
    __nv_bfloat162 t(a, b);
    return *(uint32_t*)&t;
}
// split-write a fp32 pair to hi/lo bf16 buffers (offset must be even)
__device__ __forceinline__ void wsplit(__nv_bfloat16* __restrict__ H,
                                       __nv_bfloat16* __restrict__ L,
                                       size_t o, float a, float b) {
    __nv_bfloat16 h0 = __float2bfloat16(a), h1 = __float2bfloat16(b);
    *(uint32_t*)(H + o) = pack_bf16(h0, h1);
    *(uint32_t*)(L + o) =
        pack_bf16(__float2bfloat16(a - __bfloat162float(h0)),
                  __float2bfloat16(b - __bfloat162float(h1)));
}

// ---------------------------------------------------------------------------
// fp32 -> (hi, lo) bf16 split, elementwise (vectorized x4)
// ---------------------------------------------------------------------------
__global__ __launch_bounds__(256) void split_kernel(const float* __restrict__ in,
                                                    __nv_bfloat16* __restrict__ hi,
                                                    __nv_bfloat16* __restrict__ lo,
                                                    int n4) {
    int i = blockIdx.x * blockDim.x + threadIdx.x;
    if (i >= n4) return;
    float4 v = ((const float4*)in)[i];
    __nv_bfloat16 h0 = __float2bfloat16(v.x), h1 = __float2bfloat16(v.y);
    __nv_bfloat16 h2 = __float2bfloat16(v.z), h3 = __float2bfloat16(v.w);
    __nv_bfloat16 l0 = __float2bfloat16(v.x - __bfloat162float(h0));
    __nv_bfloat16 l1 = __float2bfloat16(v.y - __bfloat162float(h1));
    __nv_bfloat16 l2 = __float2bfloat16(v.z - __bfloat162float(h2));
    __nv_bfloat16 l3 = __float2bfloat16(v.w - __bfloat162float(h3));
    ((__nv_bfloat162*)hi)[i * 2 + 0] = __nv_bfloat162(h0, h1);
    ((__nv_bfloat162*)hi)[i * 2 + 1] = __nv_bfloat162(h2, h3);
    ((__nv_bfloat162*)lo)[i * 2 + 0] = __nv_bfloat162(l0, l1);
    ((__nv_bfloat162*)lo)[i * 2 + 1] = __nv_bfloat162(l2, l3);
}

// ---------------------------------------------------------------------------
// Transpose + split: in fp32 [Kd, Nd] -> out bf16 [Nd, Kd] (hi, lo)
// ---------------------------------------------------------------------------
__global__ __launch_bounds__(256) void tsplit_kernel(const float* __restrict__ in,
                                                     __nv_bfloat16* __restrict__ oh,
                                                     __nv_bfloat16* __restrict__ ol,
                                                     int Kd, int Nd) {
    __shared__ float t[32][33];
    int n0 = blockIdx.x * 32, k0 = blockIdx.y * 32;
    int tx = threadIdx.x & 31, ty = threadIdx.x >> 5;
#pragma unroll
    for (int j = 0; j < 4; j++)
        t[ty + j * 8][tx] = in[(size_t)(k0 + ty + j * 8) * Nd + n0 + tx];
    __syncthreads();
#pragma unroll
    for (int j = 0; j < 4; j++) {
        float v = t[tx][ty + j * 8];
        __nv_bfloat16 h = __float2bfloat16(v);
        __nv_bfloat16 l = __float2bfloat16(v - __bfloat162float(h));
        size_t o = (size_t)(n0 + ty + j * 8) * Kd + k0 + tx;
        oh[o] = h;
        ol[o] = l;
    }
}

// ---------------------------------------------------------------------------
// HMMA bf16 split-precision GEMM, 2-stage cp.async pipeline (R6 structure),
// B-fragments loaded per-p to keep live regs < 128 (occ 2, no spills).
// mode 0: plain fp32 C write. mode 1: fused QKV epilogue (RoPE+scale+split).
// ---------------------------------------------------------------------------
#define GROW 40
#define GARR (128 * GROW * 2)
#define GSTAGE_B (4 * GARR)          // 40960
#define GEMM_SMEM (2 * GSTAGE_B)     // 81920

#define GLOAD(kc, st)                                                        \
    do {                                                                     \
        uint32_t uS = uBase + (st) * GSTAGE_B;                               \
        int koff = (kc) * 32;                                                \
        _Pragma("unroll") for (int t = 0; t < 2; t++) {                      \
            int idx = tid + t * 256;                                         \
            int r = idx >> 2, c8 = (idx & 3) * 8;                            \
            size_t go = (size_t)r * K + koff + c8;                           \
            uint32_t dso = (uint32_t)(r * (GROW * 2) + c8 * 2);              \
            cp16(uS + dso, gAh + go);                                        \
            cp16(uS + GARR + dso, gAl + go);                                 \
            cp16(uS + 2 * GARR + dso, gBh + go);                             \
            cp16(uS + 3 * GARR + dso, gBl + go);                             \
        }                                                                    \
    } while (0)

__global__ __launch_bounds__(256, 2) void gemm_mma(
    const __nv_bfloat16* __restrict__ Ah, const __nv_bfloat16* __restrict__ Al,
    const __nv_bfloat16* __restrict__ Bh, const __nv_bfloat16* __restrict__ Bl,
    float* __restrict__ Cf,
    __nv_bfloat16* __restrict__ Qh, __nv_bfloat16* __restrict__ Ql,
    __nv_bfloat16* __restrict__ Kh2, __nv_bfloat16* __restrict__ Kl2,
    __nv_bfloat16* __restrict__ Vh2, __nv_bfloat16* __restrict__ Vl2,
    int mode, int M, int N, int K) {
    extern __shared__ char gsm[];
    const uint32_t uBase = smem_u32(gsm);

    const int tid = threadIdx.x, wid = tid >> 5, lane = tid & 31;
    const int m0 = blockIdx.y * 128, n0 = blockIdx.x * 128;
    const int warp_m = (wid >> 2) * 64;
    const int warp_n = (wid & 3) * 32;

    const int a_roff = ((lane >> 3) & 1) * 8 + (lane & 7);
    const int a_coff = (lane >> 4) * 8;
    const int b_roff = (lane >> 4) * 8 + (lane & 7);
    const int b_coff = ((lane >> 3) & 1) * 8;

    float acc[4][4][4];
#pragma unroll
    for (int i = 0; i < 4; i++)
#pragma unroll
        for (int j = 0; j < 4; j++)
#pragma unroll
            for (int c = 0; c < 4; c++) acc[i][j][c] = 0.f;

    const __nv_bfloat16* gAh = Ah + (size_t)m0 * K;
    const __nv_bfloat16* gAl = Al + (size_t)m0 * K;
    const __nv_bfloat16* gBh = Bh + (size_t)n0 * K;
    const __nv_bfloat16* gBl = Bl + (size_t)n0 * K;

    const int KC = K >> 5;
    GLOAD(0, 0);
    cp_commit();

    for (int kc = 0; kc < KC; kc++) {
        if (kc + 1 < KC) {
            GLOAD(kc + 1, (kc + 1) & 1);
            cp_commit();
            cp_wait<1>();
        } else {
            cp_wait<0>();
        }
        __syncthreads();

        const uint32_t uS = uBase + (kc & 1) * GSTAGE_B;
        const uint32_t uAh = uS, uAl = uS + GARR;
        const uint32_t uBh = uS + 2 * GARR, uBl = uS + 3 * GARR;

#pragma unroll
        for (int ks = 0; ks < 2; ks++) {
            uint32_t ah[4][4], al[4][4];
#pragma unroll
            for (int mt = 0; mt < 4; mt++) {
                uint32_t off =
                    (uint32_t)((warp_m + mt * 16 + a_roff) * GROW +
                               ks * 16 + a_coff) * 2;
                ldsm_x4(ah[mt], uAh + off);
                ldsm_x4(al[mt], uAl + off);
            }
#pragma unroll
            for (int p = 0; p < 2; p++) {
                uint32_t bh[4], bl[4];
                uint32_t off =
                    (uint32_t)((warp_n + p * 16 + b_roff) * GROW +
                               ks * 16 + b_coff) * 2;
                ldsm_x4(bh, uBh + off);
                ldsm_x4(bl, uBl + off);
#pragma unroll
                for (int mt = 0; mt < 4; mt++) {
#pragma unroll
                    for (int hf = 0; hf < 2; hf++) {
                        float* c = acc[mt][p * 2 + hf];
                        mma16816(c, ah[mt], bh[hf * 2], bh[hf * 2 + 1]);
                        mma16816(c, ah[mt], bl[hf * 2], bl[hf * 2 + 1]);
                        mma16816(c, al[mt], bh[hf * 2], bh[hf * 2 + 1]);
                    }
                }
            }
        }
        __syncthreads();
    }

    const int cr = lane >> 2, cc = (lane & 3) * 2;
    if (mode == 0) {
#pragma unroll
        for (int mt = 0; mt < 4; mt++) {
#pragma unroll
            for (int nt = 0; nt < 4; nt++) {
                int row = m0 + warp_m + mt * 16 + cr;
                int col = n0 + warp_n + nt * 8 + cc;
                float* c = acc[mt][nt];
                *(float2*)(Cf + (size_t)row * N + col) = make_float2(c[0], c[1]);
                *(float2*)(Cf + (size_t)(row + 8) * N + col) =
                    make_float2(c[2], c[3]);
            }
        }
    } else {
        // QKV fused epilogue: col pair (col, col+1) is a RoPE rotation pair.
        // Q also folds log2(e) so flash can use raw ex2.
        const float qscale = 0.12751742f;  // log2(e)/sqrt(HD)
#pragma unroll
        for (int mt = 0; mt < 4; mt++) {
#pragma unroll
            for (int nt = 0; nt < 4; nt++) {
                int row = m0 + warp_m + mt * 16 + cr;
                int col = n0 + warp_n + nt * 8 + cc;
                float* c = acc[mt][nt];
                int s0 = row & (SS - 1);
                if (col < EE) {
                    int i = (col & (HD - 1)) >> 1;
                    float f = exp2f(-(float)i * (13.287712379549449f / 64.0f));
                    float sn0, cs0, sn1, cs1;
                    sincosf((float)s0 * f, &sn0, &cs0);
                    sincosf((float)(s0 + 8) * f, &sn1, &cs1);
                    wsplit(Qh, Ql, (size_t)row * EE + col,
                           (c[0] * cs0 - c[1] * sn0) * qscale,
                           (c[0] * sn0 + c[1] * cs0) * qscale);
                    wsplit(Qh, Ql, (size_t)(row + 8) * EE + col,
                           (c[2] * cs1 - c[3] * sn1) * qscale,
                           (c[2] * sn1 + c[3] * cs1) * qscale);
                } else if (col < EE + NKV) {
                    int colk = col - EE;
                    int i = (colk & (HD - 1)) >> 1;
                    float f = exp2f(-(float)i * (13.287712379549449f / 64.0f));
                    float sn0, cs0, sn1, cs1;
                    sincosf((float)s0 * f, &sn0, &cs0);
                    sincosf((float)(s0 + 8) * f, &sn1, &cs1);
                    wsplit(Kh2, Kl2, (size_t)row * NKV + colk,
                           c[0] * cs0 - c[1] * sn0, c[0] * sn0 + c[1] * cs0);
                    wsplit(Kh2, Kl2, (size_t)(row + 8) * NKV + colk,
                           c[2] * cs1 - c[3] * sn1, c[2] * sn1 + c[3] * cs1);
                } else {
                    int colv = col - EE - NKV;
                    wsplit(Vh2, Vl2, (size_t)row * NKV + colv, c[0], c[1]);
                    wsplit(Vh2, Vl2, (size_t)(row + 8) * NKV + colv, c[2], c[3]);
                }
            }
        }
    }
}

// ---------------------------------------------------------------------------
// Flash attention on HMMA (causal, GQA, 3-pass hi/lo split)
// BQ=128 (8 warps x 16 rows), BK=64, HD=128. P in registers.
// Scores arrive pre-scaled by log2(e) -> softmax uses raw ex2.
// Epilogue writes bf16 hi/lo context directly (fused split).
// ---------------------------------------------------------------------------
#define FROW 136
#define FQ_B (128 * FROW * 2)
#define FKV_B (64 * FROW * 2)
#define FSTAGE_B (4 * FKV_B)
#define FLA_SMEM (2 * FQ_B + 2 * FSTAGE_B)   // 208896

#define KVLOAD(j, st)                                                         \
    do {                                                                      \
        uint32_t uS = uBase + 2 * FQ_B + (st) * FSTAGE_B;                     \
        _Pragma("unroll") for (int t = 0; t < 4; t++) {                       \
            int i = tid + t * 256;                                            \
            int r = i >> 4, c8 = (i & 15) << 3;                               \
            size_t g = (size_t)(b * SS + (j) * 64 + r) * NKV + kvh * HD + c8; \
            uint32_t dso = (uint32_t)(r * (FROW * 2) + c8 * 2);               \
            cp16(uS + dso, Kh + g);                                           \
            cp16(uS + FKV_B + dso, Kl + g);                                   \
            cp16(uS + 2 * FKV_B + dso, Vh + g);                               \
            cp16(uS + 3 * FKV_B + dso, Vl + g);                               \
        }                                                                     \
    } while (0)

__global__ __launch_bounds__(256) void flash_mma(
    const __nv_bfloat16* __restrict__ Qh, const __nv_bfloat16* __restrict__ Ql,
    const __nv_bfloat16* __restrict__ Kh, const __nv_bfloat16* __restrict__ Kl,
    const __nv_bfloat16* __restrict__ Vh, const __nv_bfloat16* __restrict__ Vl,
    __nv_bfloat16* __restrict__ Oh, __nv_bfloat16* __restrict__ Ol) {
    extern __shared__ char fsm[];
    const uint32_t uBase = smem_u32(fsm);
    const uint32_t uQh = uBase, uQl = uBase + FQ_B;

    const int qt = gridDim.x - 1 - blockIdx.x;   // heavy tiles first
    const int h = blockIdx.y, b = blockIdx.z;
    const int kvh = h >> 2;
    const int tid = threadIdx.x, wid = tid >> 5, lane = tid & 31;
    const int cr = lane >> 2, tc = (lane & 3) << 1;

    const int a_roff = ((lane >> 3) & 1) * 8 + (lane & 7);
    const int a_coff = (lane >> 4) * 8;
    const int b_roff = (lane >> 4) * 8 + (lane & 7);
    const int b_coff = ((lane >> 3) & 1) * 8;
    const int v_roff = ((lane >> 3) & 1) * 8 + (lane & 7);
    const int v_coff = (lane >> 4) * 8;

    {
        const size_t qbase = (size_t)(b * SS + qt * 128) * EE + h * HD;
#pragma unroll
        for (int t = 0; t < 8; t++) {
            int i = tid + t * 256;
            int r = i >> 4, c8 = (i & 15) << 3;
            size_t g = qbase + (size_t)r * EE + c8;
            uint32_t dso = (uint32_t)(r * (FROW * 2) + c8 * 2);
            cp16(uQh + dso, Qh + g);
            cp16(uQl + dso, Ql + g);
        }
        cp_commit();
    }
    KVLOAD(0, 0);
    cp_commit();

    uint32_t qh[8][4];
    float oacc[16][4];
#pragma unroll
    for (int i = 0; i < 16; i++)
#pragma unroll
        for (int c = 0; c < 4; c++) oacc[i][c] = 0.f;
    float m0 = -1e30f, m1 = -1e30f, l0 = 0.f, l1 = 0.f;

    const int border = qt * 128 + wid * 16;
    const int jmax = 2 * qt + 1;

    for (int j = 0; j <= jmax; j++) {
        if (j + 1 <= jmax) {
            KVLOAD(j + 1, (j + 1) & 1);
            cp_commit();
            cp_wait<1>();
        } else {
            cp_wait<0>();
        }
        __syncthreads();

        if (j == 0) {
#pragma unroll
            for (int ks = 0; ks < 8; ks++)
                ldsm_x4(qh[ks],
                        uQh + (uint32_t)((wid * 16 + a_roff) * FROW +
                                         ks * 16 + a_coff) * 2);
        }

        const uint32_t uS = uBase + 2 * FQ_B + (j & 1) * FSTAGE_B;
        const uint32_t uKh = uS, uKl = uS + FKV_B;
        const uint32_t uVh = uS + 2 * FKV_B, uVl = uS + 3 * FKV_B;

        if (j * 64 <= border + 15) {
            float sacc[8][4];
#pragma unroll
            for (int nt = 0; nt < 8; nt++)
#pragma unroll
                for (int c = 0; c < 4; c++) sacc[nt][c] = 0.f;

#pragma unroll
            for (int ks = 0; ks < 8; ks++) {
                uint32_t kh4[4][4], kl4[4][4], qlf[4];
#pragma unroll
                for (int p = 0; p < 4; p++) {
                    uint32_t off =
                        (uint32_t)((p * 16 + b_roff) * FROW +
                                   ks * 16 + b_coff) * 2;
                    ldsm_x4(kh4[p], uKh + off);
                    ldsm_x4(kl4[p], uKl + off);
                }
                ldsm_x4(qlf, uQl + (uint32_t)((wid * 16 + a_roff) * FROW +
                                              ks * 16 + a_coff) * 2);
#pragma unroll
                for (int p = 0; p < 4; p++)
#pragma unroll
                    for (int hf = 0; hf < 2; hf++) {
                        float* c = sacc[p * 2 + hf];
                        mma16816(c, qh[ks], kh4[p][hf * 2], kh4[p][hf * 2 + 1]);
                        mma16816(c, qh[ks], kl4[p][hf * 2], kl4[p][hf * 2 + 1]);
                        mma16816(c, qlf,    kh4[p][hf * 2], kh4[p][hf * 2 + 1]);
                    }
            }

            if (j * 64 + 63 > border) {
                int qg0 = border + cr, qg1 = qg0 + 8;
#pragma unroll
                for (int nt = 0; nt < 8; nt++) {
                    int kg = j * 64 + nt * 8 + tc;
                    if (kg > qg0) sacc[nt][0] = -1e30f;
                    if (kg + 1 > qg0) sacc[nt][1] = -1e30f;
                    if (kg > qg1) sacc[nt][2] = -1e30f;
                    if (kg + 1 > qg1) sacc[nt][3] = -1e30f;
                }
            }

            float mx0 = -1e30f, mx1 = -1e30f;
#pragma unroll
            for (int nt = 0; nt < 8; nt++) {
                mx0 = fmaxf(mx0, fmaxf(sacc[nt][0], sacc[nt][1]));
                mx1 = fmaxf(mx1, fmaxf(sacc[nt][2], sacc[nt][3]));
            }
            mx0 = fmaxf(mx0, __shfl_xor_sync(0xffffffffu, mx0, 1, 4));
            mx0 = fmaxf(mx0, __shfl_xor_sync(0xffffffffu, mx0, 2, 4));
            mx1 = fmaxf(mx1, __shfl_xor_sync(0xffffffffu, mx1, 1, 4));
            mx1 = fmaxf(mx1, __shfl_xor_sync(0xffffffffu, mx1, 2, 4));
            float mn0 = fmaxf(m0, mx0), mn1 = fmaxf(m1, mx1);
            float al0 = fex2(m0 - mn0), al1 = fex2(m1 - mn1);

            float sum0 = 0.f, sum1 = 0.f;
            uint32_t ph[8][2], pl[8][2];
#pragma unroll
            for (int nt = 0; nt < 8; nt++) {
                float p00 = fex2(sacc[nt][0] - mn0);
                float p01 = fex2(sacc[nt][1] - mn0);
                float p10 = fex2(sacc[nt][2] - mn1);
                float p11 = fex2(sacc[nt][3] - mn1);
                sum0 += p00 + p01;
                sum1 += p10 + p11;
                __nv_bfloat16 h0 = __float2bfloat16(p00), h1 = __float2bfloat16(p01);
                __nv_bfloat16 h2 = __float2bfloat16(p10), h3 = __float2bfloat16(p11);
                ph[nt][0] = pack_bf16(h0, h1);
                ph[nt][1] = pack_bf16(h2, h3);
                pl[nt][0] = pack_bf16(__float2bfloat16(p00 - __bfloat162float(h0)),
                                      __float2bfloat16(p01 - __bfloat162float(h1)));
                pl[nt][1] = pack_bf16(__float2bfloat16(p10 - __bfloat162float(h2)),
                                      __float2bfloat16(p11 - __bfloat162float(h3)));
            }
            sum0 += __shfl_xor_sync(0xffffffffu, sum0, 1, 4);
            sum0 += __shfl_xor_sync(0xffffffffu, sum0, 2, 4);
            sum1 += __shfl_xor_sync(0xffffffffu, sum1, 1, 4);
            sum1 += __shfl_xor_sync(0xffffffffu, sum1, 2, 4);
            l0 = l0 * al0 + sum0;
            l1 = l1 * al1 + sum1;
            m0 = mn0;
            m1 = mn1;
#pragma unroll
            for (int nt = 0; nt < 16; nt++) {
                oacc[nt][0] *= al0;
                oacc[nt][1] *= al0;
                oacc[nt][2] *= al1;
                oacc[nt][3] *= al1;
            }

#pragma unroll
            for (int ks = 0; ks < 4; ks++) {
                uint32_t ah4[4] = {ph[2 * ks][0], ph[2 * ks][1],
                                   ph[2 * ks + 1][0], ph[2 * ks + 1][1]};
                uint32_t alo[4] = {pl[2 * ks][0], pl[2 * ks][1],
                                   pl[2 * ks + 1][0], pl[2 * ks + 1][1]};
#pragma unroll
                for (int p = 0; p < 8; p++) {
                    uint32_t vh4[4], vl4[4];
                    uint32_t off =
                        (uint32_t)((ks * 16 + v_roff) * FROW +
                                   p * 16 + v_coff) * 2;
                    ldsm_x4_t(vh4, uVh + off);
                    ldsm_x4_t(vl4, uVl + off);
#pragma unroll
                    for (int hf = 0; hf < 2; hf++) {
                        float* c = oacc[p * 2 + hf];
                        mma16816(c, ah4, vh4[hf * 2], vh4[hf * 2 + 1]);
                        mma16816(c, ah4, vl4[hf * 2], vl4[hf * 2 + 1]);
                        mma16816(c, alo, vh4[hf * 2], vh4[hf * 2 + 1]);
                    }
                }
            }
        }
        __syncthreads();
    }

    // ---- Epilogue: normalize + split to bf16 hi/lo context ----
    float inv0 = 1.0f / l0, inv1 = 1.0f / l1;
    int row0 = qt * 128 + wid * 16 + cr;
    size_t obase = (size_t)(b * SS + row0) * EE + h * HD;
#pragma unroll
    for (int nt = 0; nt < 16; nt++) {
        int col = nt * 8 + tc;
        wsplit(Oh, Ol, obase + col, oacc[nt][0] * inv0, oacc[nt][1] * inv0);
        wsplit(Oh, Ol, obase + (size_t)8 * EE + col,
               oacc[nt][2] * inv1, oacc[nt][3] * inv1);
    }
}

// ---------------------------------------------------------------------------
// Launch
// ---------------------------------------------------------------------------
extern "C" void kernel_launch(void* const* d_in, const int* in_sizes, int n_in,
                              void* d_out, int out_size) {
    const float* x  = (const float*)d_in[0];
    const float* Wq = (const float*)d_in[1];
    const float* Wk = (const float*)d_in[2];
    const float* Wv = (const float*)d_in[3];
    const float* Wo = (const float*)d_in[4];

    __nv_bfloat16 *Xh, *Xl, *Qbh, *Qbl, *Kbh, *Kbl, *Vbh, *Vbl, *CXh, *CXl,
        *Wch, *Wcl, *Woh, *Wol;
    cudaGetSymbolAddress((void**)&Xh, g_Xh);
    cudaGetSymbolAddress((void**)&Xl, g_Xl);
    cudaGetSymbolAddress((void**)&Qbh, g_Qbh);
    cudaGetSymbolAddress((void**)&Qbl, g_Qbl);
    cudaGetSymbolAddress((void**)&Kbh, g_Kbh);
    cudaGetSymbolAddress((void**)&Kbl, g_Kbl);
    cudaGetSymbolAddress((void**)&Vbh, g_Vbh);
    cudaGetSymbolAddress((void**)&Vbl, g_Vbl);
    cudaGetSymbolAddress((void**)&CXh, g_CXh);
    cudaGetSymbolAddress((void**)&CXl, g_CXl);
    cudaGetSymbolAddress((void**)&Wch, g_Wch);
    cudaGetSymbolAddress((void**)&Wcl, g_Wcl);
    cudaGetSymbolAddress((void**)&Woh, g_Woh);
    cudaGetSymbolAddress((void**)&Wol, g_Wol);

    cudaFuncSetAttribute(gemm_mma, cudaFuncAttributeMaxDynamicSharedMemorySize,
                         GEMM_SMEM);
    cudaFuncSetAttribute(flash_mma, cudaFuncAttributeMaxDynamicSharedMemorySize,
                         FLA_SMEM);

    // Split x; transpose+split weights (QKV concat + Wo)
    split_kernel<<<(ROWS * EE / 4 + 255) / 256, 256>>>(x, Xh, Xl, ROWS * EE / 4);
    tsplit_kernel<<<dim3(EE / 32, EE / 32), 256>>>(Wq, Wch, Wcl, EE, EE);
    tsplit_kernel<<<dim3(NKV / 32, EE / 32), 256>>>(
        Wk, Wch + (size_t)EE * EE, Wcl + (size_t)EE * EE, EE, NKV);
    tsplit_kernel<<<dim3(NKV / 32, EE / 32), 256>>>(
        Wv, Wch + (size_t)(EE + NKV) * EE, Wcl + (size_t)(EE + NKV) * EE, EE, NKV);
    tsplit_kernel<<<dim3(EE / 32, EE / 32), 256>>>(Wo, Woh, Wol, EE, EE);

    // Fused QKV projection with RoPE+scale(+log2e)+split epilogue
    gemm_mma<<<dim3(NC / 128, ROWS / 128), 256, GEMM_SMEM>>>(
        Xh, Xl, Wch, Wcl, nullptr, Qbh, Qbl, Kbh, Kbl, Vbh, Vbl,
        1, ROWS, NC, EE);

    // Flash attention (epilogue writes bf16 hi/lo context)
    flash_mma<<<dim3(SS / 128, HH, BB), 256, FLA_SMEM>>>(
        Qbh, Qbl, Kbh, Kbl, Vbh, Vbl, CXh, CXl);

    // Output projection -> d_out (fp32)
    gemm_mma<<<dim3(EE / 128, ROWS / 128), 256, GEMM_SMEM>>>(
        CXh, CXl, Woh, Wol, (float*)d_out, nullptr, nullptr, nullptr, nullptr,
        nullptr, nullptr, 0, ROWS, EE, EE);
}

// round 10
// speedup vs baseline: 1.6476x; 1.3966x over previous
#include <cuda_runtime.h>
#include <cuda_fp16.h>
#include <math.h>
#include <stdint.h>

// Problem dims
#define BB 2
#define SS 2048
#define EE 2048
#define HH 16
#define KVH 4
#define HD 128
#define ROWS (BB * SS)    // 4096
#define NKV (KVH * HD)    // 512
#define NC (EE + 2 * NKV) // 3072

// ---------------------------------------------------------------------------
// Scratch (__device__ globals; no cudaMalloc allowed)
// ---------------------------------------------------------------------------
__device__ __half g_X[(size_t)ROWS * EE];        // x, fp16 single
__device__ __half g_Qb[(size_t)ROWS * EE];       // Q (rope+scale), fp16 single
__device__ __half g_Kbh[(size_t)ROWS * NKV];
__device__ __half g_Kbl[(size_t)ROWS * NKV];
__device__ __half g_Vbh[(size_t)ROWS * NKV];
__device__ __half g_Vbl[(size_t)ROWS * NKV];
__device__ __half g_CX[(size_t)ROWS * EE];       // context, fp16 single
__device__ __half g_Wch[(size_t)NC * EE];        // QKV weights concat [N,K] hi
__device__ __half g_Wcl[(size_t)NC * EE];
__device__ __half g_Woh[(size_t)EE * EE];
__device__ __half g_Wol[(size_t)EE * EE];

// ---------------------------------------------------------------------------
// MMA / cp.async helpers
// ---------------------------------------------------------------------------
__device__ __forceinline__ uint32_t smem_u32(const void* p) {
    uint32_t a;
    asm("{ .reg .u64 t; cvta.to.shared.u64 t, %1; cvt.u32.u64 %0, t; }"
        : "=r"(a) : "l"(p));
    return a;
}
__device__ __forceinline__ void ldsm_x4(uint32_t* r, uint32_t addr) {
    asm volatile("ldmatrix.sync.aligned.m8n8.x4.shared.b16 {%0,%1,%2,%3}, [%4];"
                 : "=r"(r[0]), "=r"(r[1]), "=r"(r[2]), "=r"(r[3]) : "r"(addr));
}
__device__ __forceinline__ void ldsm_x4_t(uint32_t* r, uint32_t addr) {
    asm volatile("ldmatrix.sync.aligned.m8n8.x4.trans.shared.b16 {%0,%1,%2,%3}, [%4];"
                 : "=r"(r[0]), "=r"(r[1]), "=r"(r[2]), "=r"(r[3]) : "r"(addr));
}
// fp16 HMMA m16n8k16, fp32 accumulate
__device__ __forceinline__ void mma16816h(float* c, const uint32_t* a,
                                          uint32_t b0, uint32_t b1) {
    asm volatile(
        "mma.sync.aligned.m16n8k16.row.col.f32.f16.f16.f32 "
        "{%0,%1,%2,%3}, {%4,%5,%6,%7}, {%8,%9}, {%0,%1,%2,%3};"
        : "+f"(c[0]), "+f"(c[1]), "+f"(c[2]), "+f"(c[3])
        : "r"(a[0]), "r"(a[1]), "r"(a[2]), "r"(a[3]), "r"(b0), "r"(b1));
}
__device__ __forceinline__ void cp16(uint32_t dst, const void* src) {
    asm volatile("cp.async.cg.shared.global [%0], [%1], 16;" :: "r"(dst), "l"(src));
}
__device__ __forceinline__ void cp_commit() {
    asm volatile("cp.async.commit_group;" ::: "memory");
}
template <int N> __device__ __forceinline__ void cp_wait() {
    asm volatile("cp.async.wait_group %0;" :: "n"(N) : "memory");
}
__device__ __forceinline__ float fex2(float x) {
    float r;
    asm("ex2.approx.f32 %0, %1;" : "=f"(r) : "f"(x));
    return r;
}
__device__ __forceinline__ uint32_t pack_h(__half a, __half b) {
    __half2 t(a, b);
    return *(uint32_t*)&t;
}
// write fp32 pair as fp16 single
__device__ __forceinline__ void wcvt(__half* __restrict__ H, size_t o,
                                     float a, float b) {
    *(uint32_t*)(H + o) = pack_h(__float2half_rn(a), __float2half_rn(b));
}
// write fp32 pair as fp16 hi/lo split
__device__ __forceinline__ void wsplit(__half* __restrict__ H,
                                       __half* __restrict__ L,
                                       size_t o, float a, float b) {
    __half h0 = __float2half_rn(a), h1 = __float2half_rn(b);
    *(uint32_t*)(H + o) = pack_h(h0, h1);
    *(uint32_t*)(L + o) = pack_h(__float2half_rn(a - __half2float(h0)),
                                 __float2half_rn(b - __half2float(h1)));
}

// ---------------------------------------------------------------------------
// fp32 -> fp16 single convert (vectorized x4)
// ---------------------------------------------------------------------------
__global__ __launch_bounds__(256) void cvt_kernel(const float* __restrict__ in,
                                                  __half* __restrict__ out,
                                                  int n4) {
    int i = blockIdx.x * blockDim.x + threadIdx.x;
    if (i >= n4) return;
    float4 v = ((const float4*)in)[i];
    ((__half2*)out)[i * 2 + 0] = __half2(__float2half_rn(v.x), __float2half_rn(v.y));
    ((__half2*)out)[i * 2 + 1] = __half2(__float2half_rn(v.z), __float2half_rn(v.w));
}

// ---------------------------------------------------------------------------
// Transpose + fp16 hi/lo split: fp32 [Kd, Nd] -> fp16 [Nd, Kd] (hi, lo)
// ---------------------------------------------------------------------------
__global__ __launch_bounds__(256) void tsplit_kernel(const float* __restrict__ in,
                                                     __half* __restrict__ oh,
                                                     __half* __restrict__ ol,
                                                     int Kd, int Nd) {
    __shared__ float t[32][33];
    int n0 = blockIdx.x * 32, k0 = blockIdx.y * 32;
    int tx = threadIdx.x & 31, ty = threadIdx.x >> 5;
#pragma unroll
    for (int j = 0; j < 4; j++)
        t[ty + j * 8][tx] = in[(size_t)(k0 + ty + j * 8) * Nd + n0 + tx];
    __syncthreads();
#pragma unroll
    for (int j = 0; j < 4; j++) {
        float v = t[tx][ty + j * 8];
        __half h = __float2half_rn(v);
        __half l = __float2half_rn(v - __half2float(h));
        size_t o = (size_t)(n0 + ty + j * 8) * Kd + k0 + tx;
        oh[o] = h;
        ol[o] = l;
    }
}

// ---------------------------------------------------------------------------
// fp16 2-pass split GEMM: C = A @ (Bh+Bl)^T, A fp16 single, B [N,K] hi/lo.
// 128x128 tile, 3-stage cp.async pipeline, occ 2.
// mode 0: fp32 C. mode 1: fused QKV epilogue (RoPE+scale+split).
// ---------------------------------------------------------------------------
#define GROW 40
#define GARR (128 * GROW * 2)        // 10240
#define GSTAGE_B (3 * GARR)          // 30720 (A, Bh, Bl)
#define GEMM_SMEM (3 * GSTAGE_B)     // 92160 -> occ 2

#define GLOAD(kc, st)                                                        \
    do {                                                                     \
        uint32_t uS = uBase + (st) * GSTAGE_B;                               \
        int koff = (kc) * 32;                                                \
        _Pragma("unroll") for (int t = 0; t < 2; t++) {                      \
            int idx = tid + t * 256;                                         \
            int r = idx >> 2, c8 = (idx & 3) * 8;                            \
            size_t go = (size_t)r * K + koff + c8;                           \
            uint32_t dso = (uint32_t)(r * (GROW * 2) + c8 * 2);              \
            cp16(uS + dso, gA + go);                                         \
            cp16(uS + GARR + dso, gBh + go);                                 \
            cp16(uS + 2 * GARR + dso, gBl + go);                             \
        }                                                                    \
    } while (0)

__global__ __launch_bounds__(256, 2) void gemm_mma(
    const __half* __restrict__ A,
    const __half* __restrict__ Bh, const __half* __restrict__ Bl,
    float* __restrict__ Cf,
    __half* __restrict__ Qo,
    __half* __restrict__ Kh2, __half* __restrict__ Kl2,
    __half* __restrict__ Vh2, __half* __restrict__ Vl2,
    int mode, int M, int N, int K) {
    extern __shared__ char gsm[];
    const uint32_t uBase = smem_u32(gsm);

    const int tid = threadIdx.x, wid = tid >> 5, lane = tid & 31;
    const int m0 = blockIdx.y * 128, n0 = blockIdx.x * 128;
    const int warp_m = (wid >> 2) * 64;
    const int warp_n = (wid & 3) * 32;

    const int a_roff = ((lane >> 3) & 1) * 8 + (lane & 7);
    const int a_coff = (lane >> 4) * 8;
    const int b_roff = (lane >> 4) * 8 + (lane & 7);
    const int b_coff = ((lane >> 3) & 1) * 8;

    float acc[4][4][4];
#pragma unroll
    for (int i = 0; i < 4; i++)
#pragma unroll
        for (int j = 0; j < 4; j++)
#pragma unroll
            for (int c = 0; c < 4; c++) acc[i][j][c] = 0.f;

    const __half* gA = A + (size_t)m0 * K;
    const __half* gBh = Bh + (size_t)n0 * K;
    const __half* gBl = Bl + (size_t)n0 * K;

    const int KC = K >> 5;
    GLOAD(0, 0);
    cp_commit();
    GLOAD(1, 1);
    cp_commit();

    int st = 0, stp = 2;
    for (int kc = 0; kc < KC; kc++) {
        if (kc + 1 < KC) cp_wait<1>(); else cp_wait<0>();
        __syncthreads();
        if (kc + 2 < KC) {
            GLOAD(kc + 2, stp);
            cp_commit();
        }

        const uint32_t uS = uBase + st * GSTAGE_B;
        const uint32_t uA = uS;
        const uint32_t uBh = uS + GARR, uBl = uS + 2 * GARR;

#pragma unroll
        for (int ks = 0; ks < 2; ks++) {
            uint32_t ah[4][4];
#pragma unroll
            for (int mt = 0; mt < 4; mt++) {
                uint32_t off =
                    (uint32_t)((warp_m + mt * 16 + a_roff) * GROW +
                               ks * 16 + a_coff) * 2;
                ldsm_x4(ah[mt], uA + off);
            }
#pragma unroll
            for (int p = 0; p < 2; p++) {
                uint32_t bh[4], bl[4];
                uint32_t off =
                    (uint32_t)((warp_n + p * 16 + b_roff) * GROW +
                               ks * 16 + b_coff) * 2;
                ldsm_x4(bh, uBh + off);
                ldsm_x4(bl, uBl + off);
#pragma unroll
                for (int mt = 0; mt < 4; mt++) {
#pragma unroll
                    for (int hf = 0; hf < 2; hf++) {
                        float* c = acc[mt][p * 2 + hf];
                        mma16816h(c, ah[mt], bh[hf * 2], bh[hf * 2 + 1]);
                        mma16816h(c, ah[mt], bl[hf * 2], bl[hf * 2 + 1]);
                    }
                }
            }
        }
        st = (st == 2) ? 0 : st + 1;
        stp = (stp == 2) ? 0 : stp + 1;
    }

    const int cr = lane >> 2, cc = (lane & 3) * 2;
    if (mode == 0) {
#pragma unroll
        for (int mt = 0; mt < 4; mt++) {
#pragma unroll
            for (int nt = 0; nt < 4; nt++) {
                int row = m0 + warp_m + mt * 16 + cr;
                int col = n0 + warp_n + nt * 8 + cc;
                float* c = acc[mt][nt];
                *(float2*)(Cf + (size_t)row * N + col) = make_float2(c[0], c[1]);
                *(float2*)(Cf + (size_t)(row + 8) * N + col) =
                    make_float2(c[2], c[3]);
            }
        }
    } else {
        // QKV fused epilogue: col pair (col, col+1) is a RoPE rotation pair.
        // Q folds log2(e) so flash softmax uses raw ex2.
        const float qscale = 0.12751742f;  // log2(e)/sqrt(HD)
#pragma unroll
        for (int mt = 0; mt < 4; mt++) {
#pragma unroll
            for (int nt = 0; nt < 4; nt++) {
                int row = m0 + warp_m + mt * 16 + cr;
                int col = n0 + warp_n + nt * 8 + cc;
                float* c = acc[mt][nt];
                int s0 = row & (SS - 1);
                if (col < EE) {
                    int i = (col & (HD - 1)) >> 1;
                    float f = exp2f(-(float)i * (13.287712379549449f / 64.0f));
                    float sn0, cs0, sn1, cs1;
                    sincosf((float)s0 * f, &sn0, &cs0);
                    sincosf((float)(s0 + 8) * f, &sn1, &cs1);
                    wcvt(Qo, (size_t)row * EE + col,
                         (c[0] * cs0 - c[1] * sn0) * qscale,
                         (c[0] * sn0 + c[1] * cs0) * qscale);
                    wcvt(Qo, (size_t)(row + 8) * EE + col,
                         (c[2] * cs1 - c[3] * sn1) * qscale,
                         (c[2] * sn1 + c[3] * cs1) * qscale);
                } else if (col < EE + NKV) {
                    int colk = col - EE;
                    int i = (colk & (HD - 1)) >> 1;
                    float f = exp2f(-(float)i * (13.287712379549449f / 64.0f));
                    float sn0, cs0, sn1, cs1;
                    sincosf((float)s0 * f, &sn0, &cs0);
                    sincosf((float)(s0 + 8) * f, &sn1, &cs1);
                    wsplit(Kh2, Kl2, (size_t)row * NKV + colk,
                           c[0] * cs0 - c[1] * sn0, c[0] * sn0 + c[1] * cs0);
                    wsplit(Kh2, Kl2, (size_t)(row + 8) * NKV + colk,
                           c[2] * cs1 - c[3] * sn1, c[2] * sn1 + c[3] * cs1);
                } else {
                    int colv = col - EE - NKV;
                    wsplit(Vh2, Vl2, (size_t)row * NKV + colv, c[0], c[1]);
                    wsplit(Vh2, Vl2, (size_t)(row + 8) * NKV + colv, c[2], c[3]);
                }
            }
        }
    }
}

// ---------------------------------------------------------------------------
// Flash attention, fp16 2-pass: Q single fp16, K/V hi/lo fp16, P single fp16.
// BQ=128 (8 warps x 16 rows), BK=64, HD=128. Scores pre-scaled by log2(e).
// Epilogue writes fp16 context directly.
// ---------------------------------------------------------------------------
#define FROW 136
#define FQ_B (128 * FROW * 2)        // 34816
#define FKV_B (64 * FROW * 2)        // 17408
#define FSTAGE_B (4 * FKV_B)         // 69632
#define FLA_SMEM (FQ_B + 2 * FSTAGE_B)   // 174080

#define KVLOAD(j, st)                                                         \
    do {                                                                      \
        uint32_t uS = uBase + FQ_B + (st) * FSTAGE_B;                         \
        _Pragma("unroll") for (int t = 0; t < 4; t++) {                       \
            int i = tid + t * 256;                                            \
            int r = i >> 4, c8 = (i & 15) << 3;                               \
            size_t g = (size_t)(b * SS + (j) * 64 + r) * NKV + kvh * HD + c8; \
            uint32_t dso = (uint32_t)(r * (FROW * 2) + c8 * 2);               \
            cp16(uS + dso, Kh + g);                                           \
            cp16(uS + FKV_B + dso, Kl + g);                                   \
            cp16(uS + 2 * FKV_B + dso, Vh + g);                               \
            cp16(uS + 3 * FKV_B + dso, Vl + g);                               \
        }                                                                     \
    } while (0)

__global__ __launch_bounds__(256) void flash_mma(
    const __half* __restrict__ Q,
    const __half* __restrict__ Kh, const __half* __restrict__ Kl,
    const __half* __restrict__ Vh, const __half* __restrict__ Vl,
    __half* __restrict__ O) {
    extern __shared__ char fsm[];
    const uint32_t uBase = smem_u32(fsm);
    const uint32_t uQ = uBase;

    const int qt = gridDim.x - 1 - blockIdx.x;   // heavy tiles first
    const int h = blockIdx.y, b = blockIdx.z;
    const int kvh = h >> 2;
    const int tid = threadIdx.x, wid = tid >> 5, lane = tid & 31;
    const int cr = lane >> 2, tc = (lane & 3) << 1;

    const int a_roff = ((lane >> 3) & 1) * 8 + (lane & 7);
    const int a_coff = (lane >> 4) * 8;
    const int b_roff = (lane >> 4) * 8 + (lane & 7);
    const int b_coff = ((lane >> 3) & 1) * 8;
    const int v_roff = ((lane >> 3) & 1) * 8 + (lane & 7);
    const int v_coff = (lane >> 4) * 8;

    {
        const size_t qbase = (size_t)(b * SS + qt * 128) * EE + h * HD;
#pragma unroll
        for (int t = 0; t < 8; t++) {
            int i = tid + t * 256;
            int r = i >> 4, c8 = (i & 15) << 3;
            cp16(uQ + (uint32_t)(r * (FROW * 2) + c8 * 2),
                 Q + qbase + (size_t)r * EE + c8);
        }
        cp_commit();
    }
    KVLOAD(0, 0);
    cp_commit();

    uint32_t qh[8][4];
    float oacc[16][4];
#pragma unroll
    for (int i = 0; i < 16; i++)
#pragma unroll
        for (int c = 0; c < 4; c++) oacc[i][c] = 0.f;
    float m0 = -1e30f, m1 = -1e30f, l0 = 0.f, l1 = 0.f;

    const int border = qt * 128 + wid * 16;
    const int jmax = 2 * qt + 1;

    for (int j = 0; j <= jmax; j++) {
        if (j + 1 <= jmax) {
            KVLOAD(j + 1, (j + 1) & 1);
            cp_commit();
            cp_wait<1>();
        } else {
            cp_wait<0>();
        }
        __syncthreads();

        if (j == 0) {
#pragma unroll
            for (int ks = 0; ks < 8; ks++)
                ldsm_x4(qh[ks],
                        uQ + (uint32_t)((wid * 16 + a_roff) * FROW +
                                        ks * 16 + a_coff) * 2);
        }

        const uint32_t uS = uBase + FQ_B + (j & 1) * FSTAGE_B;
        const uint32_t uKh = uS, uKl = uS + FKV_B;
        const uint32_t uVh = uS + 2 * FKV_B, uVl = uS + 3 * FKV_B;

        if (j * 64 <= border + 15) {
            // ---- Scores S = Q @ (Kh+Kl)^T ----
            float sacc[8][4];
#pragma unroll
            for (int nt = 0; nt < 8; nt++)
#pragma unroll
                for (int c = 0; c < 4; c++) sacc[nt][c] = 0.f;

#pragma unroll
            for (int ks = 0; ks < 8; ks++) {
#pragma unroll
                for (int p = 0; p < 4; p++) {
                    uint32_t kh4[4], kl4[4];
                    uint32_t off =
                        (uint32_t)((p * 16 + b_roff) * FROW +
                                   ks * 16 + b_coff) * 2;
                    ldsm_x4(kh4, uKh + off);
                    ldsm_x4(kl4, uKl + off);
#pragma unroll
                    for (int hf = 0; hf < 2; hf++) {
                        float* c = sacc[p * 2 + hf];
                        mma16816h(c, qh[ks], kh4[hf * 2], kh4[hf * 2 + 1]);
                        mma16816h(c, qh[ks], kl4[hf * 2], kl4[hf * 2 + 1]);
                    }
                }
            }

            if (j * 64 + 63 > border) {
                int qg0 = border + cr, qg1 = qg0 + 8;
#pragma unroll
                for (int nt = 0; nt < 8; nt++) {
                    int kg = j * 64 + nt * 8 + tc;
                    if (kg > qg0) sacc[nt][0] = -1e30f;
                    if (kg + 1 > qg0) sacc[nt][1] = -1e30f;
                    if (kg > qg1) sacc[nt][2] = -1e30f;
                    if (kg + 1 > qg1) sacc[nt][3] = -1e30f;
                }
            }

            float mx0 = -1e30f, mx1 = -1e30f;
#pragma unroll
            for (int nt = 0; nt < 8; nt++) {
                mx0 = fmaxf(mx0, fmaxf(sacc[nt][0], sacc[nt][1]));
                mx1 = fmaxf(mx1, fmaxf(sacc[nt][2], sacc[nt][3]));
            }
            mx0 = fmaxf(mx0, __shfl_xor_sync(0xffffffffu, mx0, 1, 4));
            mx0 = fmaxf(mx0, __shfl_xor_sync(0xffffffffu, mx0, 2, 4));
            mx1 = fmaxf(mx1, __shfl_xor_sync(0xffffffffu, mx1, 1, 4));
            mx1 = fmaxf(mx1, __shfl_xor_sync(0xffffffffu, mx1, 2, 4));
            float mn0 = fmaxf(m0, mx0), mn1 = fmaxf(m1, mx1);
            float al0 = fex2(m0 - mn0), al1 = fex2(m1 - mn1);

            float sum0 = 0.f, sum1 = 0.f;
            uint32_t ph[8][2];
#pragma unroll
            for (int nt = 0; nt < 8; nt++) {
                float p00 = fex2(sacc[nt][0] - mn0);
                float p01 = fex2(sacc[nt][1] - mn0);
                float p10 = fex2(sacc[nt][2] - mn1);
                float p11 = fex2(sacc[nt][3] - mn1);
                sum0 += p00 + p01;
                sum1 += p10 + p11;
                ph[nt][0] = pack_h(__float2half_rn(p00), __float2half_rn(p01));
                ph[nt][1] = pack_h(__float2half_rn(p10), __float2half_rn(p11));
            }
            sum0 += __shfl_xor_sync(0xffffffffu, sum0, 1, 4);
            sum0 += __shfl_xor_sync(0xffffffffu, sum0, 2, 4);
            sum1 += __shfl_xor_sync(0xffffffffu, sum1, 1, 4);
            sum1 += __shfl_xor_sync(0xffffffffu, sum1, 2, 4);
            l0 = l0 * al0 + sum0;
            l1 = l1 * al1 + sum1;
            m0 = mn0;
            m1 = mn1;
#pragma unroll
            for (int nt = 0; nt < 16; nt++) {
                oacc[nt][0] *= al0;
                oacc[nt][1] *= al0;
                oacc[nt][2] *= al1;
                oacc[nt][3] *= al1;
            }

            // ---- O += P @ (Vh+Vl), P single fp16 ----
#pragma unroll
            for (int ks = 0; ks < 4; ks++) {
                uint32_t ah4[4] = {ph[2 * ks][0], ph[2 * ks][1],
                                   ph[2 * ks + 1][0], ph[2 * ks + 1][1]};
#pragma unroll
                for (int p = 0; p < 8; p++) {
                    uint32_t vh4[4], vl4[4];
                    uint32_t off =
                        (uint32_t)((ks * 16 + v_roff) * FROW +
                                   p * 16 + v_coff) * 2;
                    ldsm_x4_t(vh4, uVh + off);
                    ldsm_x4_t(vl4, uVl + off);
#pragma unroll
                    for (int hf = 0; hf < 2; hf++) {
                        float* c = oacc[p * 2 + hf];
                        mma16816h(c, ah4, vh4[hf * 2], vh4[hf * 2 + 1]);
                        mma16816h(c, ah4, vl4[hf * 2], vl4[hf * 2 + 1]);
                    }
                }
            }
        }
        __syncthreads();
    }

    // ---- Epilogue: normalize + fp16 context ----
    float inv0 = 1.0f / l0, inv1 = 1.0f / l1;
    int row0 = qt * 128 + wid * 16 + cr;
    size_t obase = (size_t)(b * SS + row0) * EE + h * HD;
#pragma unroll
    for (int nt = 0; nt < 16; nt++) {
        int col = nt * 8 + tc;
        wcvt(O, obase + col, oacc[nt][0] * inv0, oacc[nt][1] * inv0);
        wcvt(O, obase + (size_t)8 * EE + col,
             oacc[nt][2] * inv1, oacc[nt][3] * inv1);
    }
}

// ---------------------------------------------------------------------------
// Launch
// ---------------------------------------------------------------------------
extern "C" void kernel_launch(void* const* d_in, const int* in_sizes, int n_in,
                              void* d_out, int out_size) {
    const float* x  = (const float*)d_in[0];
    const float* Wq = (const float*)d_in[1];
    const float* Wk = (const float*)d_in[2];
    const float* Wv = (const float*)d_in[3];
    const float* Wo = (const float*)d_in[4];

    __half *X, *Qb, *Kbh, *Kbl, *Vbh, *Vbl, *CX, *Wch, *Wcl, *Woh, *Wol;
    cudaGetSymbolAddress((void**)&X, g_X);
    cudaGetSymbolAddress((void**)&Qb, g_Qb);
    cudaGetSymbolAddress((void**)&Kbh, g_Kbh);
    cudaGetSymbolAddress((void**)&Kbl, g_Kbl);
    cudaGetSymbolAddress((void**)&Vbh, g_Vbh);
    cudaGetSymbolAddress((void**)&Vbl, g_Vbl);
    cudaGetSymbolAddress((void**)&CX, g_CX);
    cudaGetSymbolAddress((void**)&Wch, g_Wch);
    cudaGetSymbolAddress((void**)&Wcl, g_Wcl);
    cudaGetSymbolAddress((void**)&Woh, g_Woh);
    cudaGetSymbolAddress((void**)&Wol, g_Wol);

    cudaFuncSetAttribute(gemm_mma, cudaFuncAttributeMaxDynamicSharedMemorySize,
                         GEMM_SMEM);
    cudaFuncSetAttribute(flash_mma, cudaFuncAttributeMaxDynamicSharedMemorySize,
                         FLA_SMEM);

    // Convert x; transpose+split weights (QKV concat + Wo)
    cvt_kernel<<<(ROWS * EE / 4 + 255) / 256, 256>>>(x, X, ROWS * EE / 4);
    tsplit_kernel<<<dim3(EE / 32, EE / 32), 256>>>(Wq, Wch, Wcl, EE, EE);
    tsplit_kernel<<<dim3(NKV / 32, EE / 32), 256>>>(
        Wk, Wch + (size_t)EE * EE, Wcl + (size_t)EE * EE, EE, NKV);
    tsplit_kernel<<<dim3(NKV / 32, EE / 32), 256>>>(
        Wv, Wch + (size_t)(EE + NKV) * EE, Wcl + (size_t)(EE + NKV) * EE, EE, NKV);
    tsplit_kernel<<<dim3(EE / 32, EE / 32), 256>>>(Wo, Woh, Wol, EE, EE);

    // Fused QKV projection with RoPE+scale(+log2e)+split epilogue
    gemm_mma<<<dim3(NC / 128, ROWS / 128), 256, GEMM_SMEM>>>(
        X, Wch, Wcl, nullptr, Qb, Kbh, Kbl, Vbh, Vbl, 1, ROWS, NC, EE);

    // Flash attention (epilogue writes fp16 context)
    flash_mma<<<dim3(SS / 128, HH, BB), 256, FLA_SMEM>>>(
        Qb, Kbh, Kbl, Vbh, Vbl, CX);

    // Output projection -> d_out (fp32)
    gemm_mma<<<dim3(EE / 128, ROWS / 128), 256, GEMM_SMEM>>>(
        CX, Woh, Wol, (float*)d_out, nullptr, nullptr, nullptr, nullptr,
        nullptr, 0, ROWS, EE, EE);
}

// round 11
// speedup vs baseline: 1.8992x; 1.1527x over previous
#include <cuda_runtime.h>
#include <cuda_fp16.h>
#include <math.h>
#include <stdint.h>

// Problem dims
#define BB 2
#define SS 2048
#define EE 2048
#define HH 16
#define KVH 4
#define HD 128
#define ROWS (BB * SS)    // 4096
#define NKV (KVH * HD)    // 512
#define NC (EE + 2 * NKV) // 3072

// ---------------------------------------------------------------------------
// Scratch (__device__ globals; no cudaMalloc allowed)
// ---------------------------------------------------------------------------
__device__ __half g_X[(size_t)ROWS * EE];        // x, fp16 single
__device__ __half g_Qb[(size_t)ROWS * EE];       // Q (rope+scale), fp16 single
__device__ __half g_Kb[(size_t)ROWS * NKV];      // K (rope), fp16 single
__device__ __half g_Vb[(size_t)ROWS * NKV];      // V, fp16 single
__device__ __half g_CX[(size_t)ROWS * EE];       // context, fp16 single
__device__ __half g_Wch[(size_t)NC * EE];        // QKV weights concat [N,K] hi
__device__ __half g_Wcl[(size_t)NC * EE];
__device__ __half g_Woh[(size_t)EE * EE];
__device__ __half g_Wol[(size_t)EE * EE];

// ---------------------------------------------------------------------------
// MMA / cp.async helpers
// ---------------------------------------------------------------------------
__device__ __forceinline__ uint32_t smem_u32(const void* p) {
    uint32_t a;
    asm("{ .reg .u64 t; cvta.to.shared.u64 t, %1; cvt.u32.u64 %0, t; }"
        : "=r"(a) : "l"(p));
    return a;
}
__device__ __forceinline__ void ldsm_x4(uint32_t* r, uint32_t addr) {
    asm volatile("ldmatrix.sync.aligned.m8n8.x4.shared.b16 {%0,%1,%2,%3}, [%4];"
                 : "=r"(r[0]), "=r"(r[1]), "=r"(r[2]), "=r"(r[3]) : "r"(addr));
}
__device__ __forceinline__ void ldsm_x4_t(uint32_t* r, uint32_t addr) {
    asm volatile("ldmatrix.sync.aligned.m8n8.x4.trans.shared.b16 {%0,%1,%2,%3}, [%4];"
                 : "=r"(r[0]), "=r"(r[1]), "=r"(r[2]), "=r"(r[3]) : "r"(addr));
}
// fp16 HMMA m16n8k16, fp32 accumulate
__device__ __forceinline__ void mma16816h(float* c, const uint32_t* a,
                                          uint32_t b0, uint32_t b1) {
    asm volatile(
        "mma.sync.aligned.m16n8k16.row.col.f32.f16.f16.f32 "
        "{%0,%1,%2,%3}, {%4,%5,%6,%7}, {%8,%9}, {%0,%1,%2,%3};"
        : "+f"(c[0]), "+f"(c[1]), "+f"(c[2]), "+f"(c[3])
        : "r"(a[0]), "r"(a[1]), "r"(a[2]), "r"(a[3]), "r"(b0), "r"(b1));
}
__device__ __forceinline__ void cp16(uint32_t dst, const void* src) {
    asm volatile("cp.async.cg.shared.global [%0], [%1], 16;" :: "r"(dst), "l"(src));
}
__device__ __forceinline__ void cp_commit() {
    asm volatile("cp.async.commit_group;" ::: "memory");
}
template <int N> __device__ __forceinline__ void cp_wait() {
    asm volatile("cp.async.wait_group %0;" :: "n"(N) : "memory");
}
__device__ __forceinline__ float fex2(float x) {
    float r;
    asm("ex2.approx.f32 %0, %1;" : "=f"(r) : "f"(x));
    return r;
}
__device__ __forceinline__ uint32_t pack_h(__half a, __half b) {
    __half2 t(a, b);
    return *(uint32_t*)&t;
}
// write fp32 pair as fp16 single
__device__ __forceinline__ void wcvt(__half* __restrict__ H, size_t o,
                                     float a, float b) {
    *(uint32_t*)(H + o) = pack_h(__float2half_rn(a), __float2half_rn(b));
}
// write fp32 pair as fp16 hi/lo split
__device__ __forceinline__ void wsplit(__half* __restrict__ H,
                                       __half* __restrict__ L,
                                       size_t o, float a, float b) {
    __half h0 = __float2half_rn(a), h1 = __float2half_rn(b);
    *(uint32_t*)(H + o) = pack_h(h0, h1);
    *(uint32_t*)(L + o) = pack_h(__float2half_rn(a - __half2float(h0)),
                                 __float2half_rn(b - __half2float(h1)));
}

// ---------------------------------------------------------------------------
// fp32 -> fp16 single convert (vectorized x4)
// ---------------------------------------------------------------------------
__global__ __launch_bounds__(256) void cvt_kernel(const float* __restrict__ in,
                                                  __half* __restrict__ out,
                                                  int n4) {
    int i = blockIdx.x * blockDim.x + threadIdx.x;
    if (i >= n4) return;
    float4 v = ((const float4*)in)[i];
    ((__half2*)out)[i * 2 + 0] = __half2(__float2half_rn(v.x), __float2half_rn(v.y));
    ((__half2*)out)[i * 2 + 1] = __half2(__float2half_rn(v.z), __float2half_rn(v.w));
}

// ---------------------------------------------------------------------------
// Transpose + fp16 hi/lo split: fp32 [Kd, Nd] -> fp16 [Nd, Kd] (hi, lo)
// ---------------------------------------------------------------------------
__global__ __launch_bounds__(256) void tsplit_kernel(const float* __restrict__ in,
                                                     __half* __restrict__ oh,
                                                     __half* __restrict__ ol,
                                                     int Kd, int Nd) {
    __shared__ float t[32][33];
    int n0 = blockIdx.x * 32, k0 = blockIdx.y * 32;
    int tx = threadIdx.x & 31, ty = threadIdx.x >> 5;
#pragma unroll
    for (int j = 0; j < 4; j++)
        t[ty + j * 8][tx] = in[(size_t)(k0 + ty + j * 8) * Nd + n0 + tx];
    __syncthreads();
#pragma unroll
    for (int j = 0; j < 4; j++) {
        float v = t[tx][ty + j * 8];
        __half h = __float2half_rn(v);
        __half l = __float2half_rn(v - __half2float(h));
        size_t o = (size_t)(n0 + ty + j * 8) * Kd + k0 + tx;
        oh[o] = h;
        ol[o] = l;
    }
}

// ---------------------------------------------------------------------------
// fp16 2-pass split GEMM: C = A @ (Bh+Bl)^T, A fp16 single, B [N,K] hi/lo.
// 128x128 tile, 3-stage cp.async pipeline, occ 2.
// mode 0: fp32 C. mode 1: fused QKV epilogue (RoPE+scale, fp16 single out).
// ---------------------------------------------------------------------------
#define GROW 40
#define GARR (128 * GROW * 2)        // 10240
#define GSTAGE_B (3 * GARR)          // 30720 (A, Bh, Bl)
#define GEMM_SMEM (3 * GSTAGE_B)     // 92160 -> occ 2

#define GLOAD(kc, st)                                                        \
    do {                                                                     \
        uint32_t uS = uBase + (st) * GSTAGE_B;                               \
        int koff = (kc) * 32;                                                \
        _Pragma("unroll") for (int t = 0; t < 2; t++) {                      \
            int idx = tid + t * 256;                                         \
            int r = idx >> 2, c8 = (idx & 3) * 8;                            \
            size_t go = (size_t)r * K + koff + c8;                           \
            uint32_t dso = (uint32_t)(r * (GROW * 2) + c8 * 2);              \
            cp16(uS + dso, gA + go);                                         \
            cp16(uS + GARR + dso, gBh + go);                                 \
            cp16(uS + 2 * GARR + dso, gBl + go);                             \
        }                                                                    \
    } while (0)

__global__ __launch_bounds__(256, 2) void gemm_mma(
    const __half* __restrict__ A,
    const __half* __restrict__ Bh, const __half* __restrict__ Bl,
    float* __restrict__ Cf,
    __half* __restrict__ Qo, __half* __restrict__ Ko, __half* __restrict__ Vo,
    int mode, int M, int N, int K) {
    extern __shared__ char gsm[];
    const uint32_t uBase = smem_u32(gsm);

    const int tid = threadIdx.x, wid = tid >> 5, lane = tid & 31;
    const int m0 = blockIdx.y * 128, n0 = blockIdx.x * 128;
    const int warp_m = (wid >> 2) * 64;
    const int warp_n = (wid & 3) * 32;

    const int a_roff = ((lane >> 3) & 1) * 8 + (lane & 7);
    const int a_coff = (lane >> 4) * 8;
    const int b_roff = (lane >> 4) * 8 + (lane & 7);
    const int b_coff = ((lane >> 3) & 1) * 8;

    float acc[4][4][4];
#pragma unroll
    for (int i = 0; i < 4; i++)
#pragma unroll
        for (int j = 0; j < 4; j++)
#pragma unroll
            for (int c = 0; c < 4; c++) acc[i][j][c] = 0.f;

    const __half* gA = A + (size_t)m0 * K;
    const __half* gBh = Bh + (size_t)n0 * K;
    const __half* gBl = Bl + (size_t)n0 * K;

    const int KC = K >> 5;
    GLOAD(0, 0);
    cp_commit();
    GLOAD(1, 1);
    cp_commit();

    int st = 0, stp = 2;
    for (int kc = 0; kc < KC; kc++) {
        if (kc + 1 < KC) cp_wait<1>(); else cp_wait<0>();
        __syncthreads();
        if (kc + 2 < KC) {
            GLOAD(kc + 2, stp);
            cp_commit();
        }

        const uint32_t uS = uBase + st * GSTAGE_B;
        const uint32_t uA = uS;
        const uint32_t uBh = uS + GARR, uBl = uS + 2 * GARR;

#pragma unroll
        for (int ks = 0; ks < 2; ks++) {
            uint32_t ah[4][4];
#pragma unroll
            for (int mt = 0; mt < 4; mt++) {
                uint32_t off =
                    (uint32_t)((warp_m + mt * 16 + a_roff) * GROW +
                               ks * 16 + a_coff) * 2;
                ldsm_x4(ah[mt], uA + off);
            }
#pragma unroll
            for (int p = 0; p < 2; p++) {
                uint32_t bh[4], bl[4];
                uint32_t off =
                    (uint32_t)((warp_n + p * 16 + b_roff) * GROW +
                               ks * 16 + b_coff) * 2;
                ldsm_x4(bh, uBh + off);
                ldsm_x4(bl, uBl + off);
#pragma unroll
                for (int mt = 0; mt < 4; mt++) {
#pragma unroll
                    for (int hf = 0; hf < 2; hf++) {
                        float* c = acc[mt][p * 2 + hf];
                        mma16816h(c, ah[mt], bh[hf * 2], bh[hf * 2 + 1]);
                        mma16816h(c, ah[mt], bl[hf * 2], bl[hf * 2 + 1]);
                    }
                }
            }
        }
        st = (st == 2) ? 0 : st + 1;
        stp = (stp == 2) ? 0 : stp + 1;
    }

    const int cr = lane >> 2, cc = (lane & 3) * 2;
    if (mode == 0) {
#pragma unroll
        for (int mt = 0; mt < 4; mt++) {
#pragma unroll
            for (int nt = 0; nt < 4; nt++) {
                int row = m0 + warp_m + mt * 16 + cr;
                int col = n0 + warp_n + nt * 8 + cc;
                float* c = acc[mt][nt];
                *(float2*)(Cf + (size_t)row * N + col) = make_float2(c[0], c[1]);
                *(float2*)(Cf + (size_t)(row + 8) * N + col) =
                    make_float2(c[2], c[3]);
            }
        }
    } else {
        // QKV fused epilogue: col pair (col, col+1) is a RoPE rotation pair.
        // Q folds log2(e) so flash softmax uses raw ex2. All outputs fp16 single.
        const float qscale = 0.12751742f;  // log2(e)/sqrt(HD)
#pragma unroll
        for (int mt = 0; mt < 4; mt++) {
#pragma unroll
            for (int nt = 0; nt < 4; nt++) {
                int row = m0 + warp_m + mt * 16 + cr;
                int col = n0 + warp_n + nt * 8 + cc;
                float* c = acc[mt][nt];
                int s0 = row & (SS - 1);
                if (col < EE) {
                    int i = (col & (HD - 1)) >> 1;
                    float f = exp2f(-(float)i * (13.287712379549449f / 64.0f));
                    float sn0, cs0, sn1, cs1;
                    sincosf((float)s0 * f, &sn0, &cs0);
                    sincosf((float)(s0 + 8) * f, &sn1, &cs1);
                    wcvt(Qo, (size_t)row * EE + col,
                         (c[0] * cs0 - c[1] * sn0) * qscale,
                         (c[0] * sn0 + c[1] * cs0) * qscale);
                    wcvt(Qo, (size_t)(row + 8) * EE + col,
                         (c[2] * cs1 - c[3] * sn1) * qscale,
                         (c[2] * sn1 + c[3] * cs1) * qscale);
                } else if (col < EE + NKV) {
                    int colk = col - EE;
                    int i = (colk & (HD - 1)) >> 1;
                    float f = exp2f(-(float)i * (13.287712379549449f / 64.0f));
                    float sn0, cs0, sn1, cs1;
                    sincosf((float)s0 * f, &sn0, &cs0);
                    sincosf((float)(s0 + 8) * f, &sn1, &cs1);
                    wcvt(Ko, (size_t)row * NKV + colk,
                         c[0] * cs0 - c[1] * sn0, c[0] * sn0 + c[1] * cs0);
                    wcvt(Ko, (size_t)(row + 8) * NKV + colk,
                         c[2] * cs1 - c[3] * sn1, c[2] * sn1 + c[3] * cs1);
                } else {
                    int colv = col - EE - NKV;
                    wcvt(Vo, (size_t)row * NKV + colv, c[0], c[1]);
                    wcvt(Vo, (size_t)(row + 8) * NKV + colv, c[2], c[3]);
                }
            }
        }
    }
}

// ---------------------------------------------------------------------------
// Flash attention, all-fp16-single MMA: Q, K, V, P single fp16, fp32 accum.
// BQ=128 (8 warps x 16 rows), BK=64, HD=128. Scores pre-scaled by log2(e).
// smem: Q 34816 + 2 stages x {K,V} 34816 = 104448 -> occ 2 (regs <= 128:
// Q fragments re-loaded from smem per tile instead of hoisted).
// ---------------------------------------------------------------------------
#define FROW 136
#define FQ_B (128 * FROW * 2)        // 34816
#define FKV_B (64 * FROW * 2)        // 17408
#define FSTAGE_B (2 * FKV_B)         // 34816
#define FLA_SMEM (FQ_B + 2 * FSTAGE_B)   // 104448

#define KVLOAD(j, st)                                                         \
    do {                                                                      \
        uint32_t uS = uBase + FQ_B + (st) * FSTAGE_B;                         \
        _Pragma("unroll") for (int t = 0; t < 4; t++) {                       \
            int i = tid + t * 256;                                            \
            int r = i >> 4, c8 = (i & 15) << 3;                               \
            size_t g = (size_t)(b * SS + (j) * 64 + r) * NKV + kvh * HD + c8; \
            uint32_t dso = (uint32_t)(r * (FROW * 2) + c8 * 2);               \
            cp16(uS + dso, Kk + g);                                           \
            cp16(uS + FKV_B + dso, Vv + g);                                   \
        }                                                                     \
    } while (0)

__global__ __launch_bounds__(256, 2) void flash_mma(
    const __half* __restrict__ Q,
    const __half* __restrict__ Kk, const __half* __restrict__ Vv,
    __half* __restrict__ O) {
    extern __shared__ char fsm[];
    const uint32_t uBase = smem_u32(fsm);
    const uint32_t uQ = uBase;

    const int qt = gridDim.x - 1 - blockIdx.x;   // heavy tiles first
    const int h = blockIdx.y, b = blockIdx.z;
    const int kvh = h >> 2;
    const int tid = threadIdx.x, wid = tid >> 5, lane = tid & 31;
    const int cr = lane >> 2, tc = (lane & 3) << 1;

    const int a_roff = ((lane >> 3) & 1) * 8 + (lane & 7);
    const int a_coff = (lane >> 4) * 8;
    const int b_roff = (lane >> 4) * 8 + (lane & 7);
    const int b_coff = ((lane >> 3) & 1) * 8;
    const int v_roff = ((lane >> 3) & 1) * 8 + (lane & 7);
    const int v_coff = (lane >> 4) * 8;

    {
        const size_t qbase = (size_t)(b * SS + qt * 128) * EE + h * HD;
#pragma unroll
        for (int t = 0; t < 8; t++) {
            int i = tid + t * 256;
            int r = i >> 4, c8 = (i & 15) << 3;
            cp16(uQ + (uint32_t)(r * (FROW * 2) + c8 * 2),
                 Q + qbase + (size_t)r * EE + c8);
        }
        cp_commit();
    }
    KVLOAD(0, 0);
    cp_commit();

    float oacc[16][4];
#pragma unroll
    for (int i = 0; i < 16; i++)
#pragma unroll
        for (int c = 0; c < 4; c++) oacc[i][c] = 0.f;
    float m0 = -1e30f, m1 = -1e30f, l0 = 0.f, l1 = 0.f;

    const int border = qt * 128 + wid * 16;
    const int jmax = 2 * qt + 1;

    for (int j = 0; j <= jmax; j++) {
        if (j + 1 <= jmax) {
            KVLOAD(j + 1, (j + 1) & 1);
            cp_commit();
            cp_wait<1>();
        } else {
            cp_wait<0>();
        }
        __syncthreads();

        const uint32_t uS = uBase + FQ_B + (j & 1) * FSTAGE_B;
        const uint32_t uK = uS, uV = uS + FKV_B;

        if (j * 64 <= border + 15) {
            // ---- Scores S = Q @ K^T ----
            float sacc[8][4];
#pragma unroll
            for (int nt = 0; nt < 8; nt++)
#pragma unroll
                for (int c = 0; c < 4; c++) sacc[nt][c] = 0.f;

#pragma unroll
            for (int ks = 0; ks < 8; ks++) {
                uint32_t qf[4];
                ldsm_x4(qf, uQ + (uint32_t)((wid * 16 + a_roff) * FROW +
                                            ks * 16 + a_coff) * 2);
#pragma unroll
                for (int p = 0; p < 4; p++) {
                    uint32_t kf[4];
                    uint32_t off =
                        (uint32_t)((p * 16 + b_roff) * FROW +
                                   ks * 16 + b_coff) * 2;
                    ldsm_x4(kf, uK + off);
#pragma unroll
                    for (int hf = 0; hf < 2; hf++)
                        mma16816h(sacc[p * 2 + hf], qf, kf[hf * 2], kf[hf * 2 + 1]);
                }
            }

            if (j * 64 + 63 > border) {
                int qg0 = border + cr, qg1 = qg0 + 8;
#pragma unroll
                for (int nt = 0; nt < 8; nt++) {
                    int kg = j * 64 + nt * 8 + tc;
                    if (kg > qg0) sacc[nt][0] = -1e30f;
                    if (kg + 1 > qg0) sacc[nt][1] = -1e30f;
                    if (kg > qg1) sacc[nt][2] = -1e30f;
                    if (kg + 1 > qg1) sacc[nt][3] = -1e30f;
                }
            }

            float mx0 = -1e30f, mx1 = -1e30f;
#pragma unroll
            for (int nt = 0; nt < 8; nt++) {
                mx0 = fmaxf(mx0, fmaxf(sacc[nt][0], sacc[nt][1]));
                mx1 = fmaxf(mx1, fmaxf(sacc[nt][2], sacc[nt][3]));
            }
            mx0 = fmaxf(mx0, __shfl_xor_sync(0xffffffffu, mx0, 1, 4));
            mx0 = fmaxf(mx0, __shfl_xor_sync(0xffffffffu, mx0, 2, 4));
            mx1 = fmaxf(mx1, __shfl_xor_sync(0xffffffffu, mx1, 1, 4));
            mx1 = fmaxf(mx1, __shfl_xor_sync(0xffffffffu, mx1, 2, 4));
            float mn0 = fmaxf(m0, mx0), mn1 = fmaxf(m1, mx1);
            float al0 = fex2(m0 - mn0), al1 = fex2(m1 - mn1);

            float sum0 = 0.f, sum1 = 0.f;
            uint32_t ph[8][2];
#pragma unroll
            for (int nt = 0; nt < 8; nt++) {
                float p00 = fex2(sacc[nt][0] - mn0);
                float p01 = fex2(sacc[nt][1] - mn0);
                float p10 = fex2(sacc[nt][2] - mn1);
                float p11 = fex2(sacc[nt][3] - mn1);
                sum0 += p00 + p01;
                sum1 += p10 + p11;
                ph[nt][0] = pack_h(__float2half_rn(p00), __float2half_rn(p01));
                ph[nt][1] = pack_h(__float2half_rn(p10), __float2half_rn(p11));
            }
            sum0 += __shfl_xor_sync(0xffffffffu, sum0, 1, 4);
            sum0 += __shfl_xor_sync(0xffffffffu, sum0, 2, 4);
            sum1 += __shfl_xor_sync(0xffffffffu, sum1, 1, 4);
            sum1 += __shfl_xor_sync(0xffffffffu, sum1, 2, 4);
            l0 = l0 * al0 + sum0;
            l1 = l1 * al1 + sum1;
            m0 = mn0;
            m1 = mn1;
#pragma unroll
            for (int nt = 0; nt < 16; nt++) {
                oacc[nt][0] *= al0;
                oacc[nt][1] *= al0;
                oacc[nt][2] *= al1;
                oacc[nt][3] *= al1;
            }

            // ---- O += P @ V ----
#pragma unroll
            for (int ks = 0; ks < 4; ks++) {
                uint32_t ah4[4] = {ph[2 * ks][0], ph[2 * ks][1],
                                   ph[2 * ks + 1][0], ph[2 * ks + 1][1]};
#pragma unroll
                for (int p = 0; p < 8; p++) {
                    uint32_t vf[4];
                    uint32_t off =
                        (uint32_t)((ks * 16 + v_roff) * FROW +
                                   p * 16 + v_coff) * 2;
                    ldsm_x4_t(vf, uV + off);
#pragma unroll
                    for (int hf = 0; hf < 2; hf++)
                        mma16816h(oacc[p * 2 + hf], ah4, vf[hf * 2], vf[hf * 2 + 1]);
                }
            }
        }
        __syncthreads();
    }

    // ---- Epilogue: normalize + fp16 context ----
    float inv0 = 1.0f / l0, inv1 = 1.0f / l1;
    int row0 = qt * 128 + wid * 16 + cr;
    size_t obase = (size_t)(b * SS + row0) * EE + h * HD;
#pragma unroll
    for (int nt = 0; nt < 16; nt++) {
        int col = nt * 8 + tc;
        wcvt(O, obase + col, oacc[nt][0] * inv0, oacc[nt][1] * inv0);
        wcvt(O, obase + (size_t)8 * EE + col,
             oacc[nt][2] * inv1, oacc[nt][3] * inv1);
    }
}

// ---------------------------------------------------------------------------
// Launch
// ---------------------------------------------------------------------------
extern "C" void kernel_launch(void* const* d_in, const int* in_sizes, int n_in,
                              void* d_out, int out_size) {
    const float* x  = (const float*)d_in[0];
    const float* Wq = (const float*)d_in[1];
    const float* Wk = (const float*)d_in[2];
    const float* Wv = (const float*)d_in[3];
    const float* Wo = (const float*)d_in[4];

    __half *X, *Qb, *Kb, *Vb, *CX, *Wch, *Wcl, *Woh, *Wol;
    cudaGetSymbolAddress((void**)&X, g_X);
    cudaGetSymbolAddress((void**)&Qb, g_Qb);
    cudaGetSymbolAddress((void**)&Kb, g_Kb);
    cudaGetSymbolAddress((void**)&Vb, g_Vb);
    cudaGetSymbolAddress((void**)&CX, g_CX);
    cudaGetSymbolAddress((void**)&Wch, g_Wch);
    cudaGetSymbolAddress((void**)&Wcl, g_Wcl);
    cudaGetSymbolAddress((void**)&Woh, g_Woh);
    cudaGetSymbolAddress((void**)&Wol, g_Wol);

    cudaFuncSetAttribute(gemm_mma, cudaFuncAttributeMaxDynamicSharedMemorySize,
                         GEMM_SMEM);
    cudaFuncSetAttribute(flash_mma, cudaFuncAttributeMaxDynamicSharedMemorySize,
                         FLA_SMEM);

    // Convert x; transpose+split weights (QKV concat + Wo)
    cvt_kernel<<<(ROWS * EE / 4 + 255) / 256, 256>>>(x, X, ROWS * EE / 4);
    tsplit_kernel<<<dim3(EE / 32, EE / 32), 256>>>(Wq, Wch, Wcl, EE, EE);
    tsplit_kernel<<<dim3(NKV / 32, EE / 32), 256>>>(
        Wk, Wch + (size_t)EE * EE, Wcl + (size_t)EE * EE, EE, NKV);
    tsplit_kernel<<<dim3(NKV / 32, EE / 32), 256>>>(
        Wv, Wch + (size_t)(EE + NKV) * EE, Wcl + (size_t)(EE + NKV) * EE, EE, NKV);
    tsplit_kernel<<<dim3(EE / 32, EE / 32), 256>>>(Wo, Woh, Wol, EE, EE);

    // Fused QKV projection with RoPE+scale(+log2e) epilogue (fp16 out)
    gemm_mma<<<dim3(NC / 128, ROWS / 128), 256, GEMM_SMEM>>>(
        X, Wch, Wcl, nullptr, Qb, Kb, Vb, 1, ROWS, NC, EE);

    // Flash attention (fp16 single everywhere, fp32 accum), occ 2
    flash_mma<<<dim3(SS / 128, HH, BB), 256, FLA_SMEM>>>(Qb, Kb, Vb, CX);

    // Output projection -> d_out (fp32)
    gemm_mma<<<dim3(EE / 128, ROWS / 128), 256, GEMM_SMEM>>>(
        CX, Woh, Wol, (float*)d_out, nullptr, nullptr, nullptr,
        0, ROWS, EE, EE);
}

// round 12
// speedup vs baseline: 2.6488x; 1.3947x over previous
#include <cuda_runtime.h>
#include <cuda_fp16.h>
#include <math.h>
#include <stdint.h>

// Problem dims
#define BB 2
#define SS 2048
#define EE 2048
#define HH 16
#define KVH 4
#define HD 128
#define ROWS (BB * SS)    // 4096
#define NKV (KVH * HD)    // 512
#define NC (EE + 2 * NKV) // 3072

// ---------------------------------------------------------------------------
// Scratch (__device__ globals; no cudaMalloc allowed)
// ---------------------------------------------------------------------------
__device__ __half g_X[(size_t)ROWS * EE];        // x, fp16
__device__ __half g_Qb[(size_t)ROWS * EE];       // Q (rope+scale), fp16
__device__ __half g_Kb[(size_t)ROWS * NKV];      // K (rope), fp16
__device__ __half g_Vb[(size_t)ROWS * NKV];      // V, fp16
__device__ __half g_CX[(size_t)ROWS * EE];       // context, fp16
__device__ __half g_Wc[(size_t)NC * EE];         // QKV weights concat [N,K]
__device__ __half g_Wo[(size_t)EE * EE];         // Wo [N,K]

// ---------------------------------------------------------------------------
// MMA / cp.async helpers
// ---------------------------------------------------------------------------
__device__ __forceinline__ uint32_t smem_u32(const void* p) {
    uint32_t a;
    asm("{ .reg .u64 t; cvta.to.shared.u64 t, %1; cvt.u32.u64 %0, t; }"
        : "=r"(a) : "l"(p));
    return a;
}
__device__ __forceinline__ void ldsm_x4(uint32_t* r, uint32_t addr) {
    asm volatile("ldmatrix.sync.aligned.m8n8.x4.shared.b16 {%0,%1,%2,%3}, [%4];"
                 : "=r"(r[0]), "=r"(r[1]), "=r"(r[2]), "=r"(r[3]) : "r"(addr));
}
__device__ __forceinline__ void ldsm_x4_t(uint32_t* r, uint32_t addr) {
    asm volatile("ldmatrix.sync.aligned.m8n8.x4.trans.shared.b16 {%0,%1,%2,%3}, [%4];"
                 : "=r"(r[0]), "=r"(r[1]), "=r"(r[2]), "=r"(r[3]) : "r"(addr));
}
// fp16 HMMA m16n8k16, fp32 accumulate
__device__ __forceinline__ void mma16816h(float* c, const uint32_t* a,
                                          uint32_t b0, uint32_t b1) {
    asm volatile(
        "mma.sync.aligned.m16n8k16.row.col.f32.f16.f16.f32 "
        "{%0,%1,%2,%3}, {%4,%5,%6,%7}, {%8,%9}, {%0,%1,%2,%3};"
        : "+f"(c[0]), "+f"(c[1]), "+f"(c[2]), "+f"(c[3])
        : "r"(a[0]), "r"(a[1]), "r"(a[2]), "r"(a[3]), "r"(b0), "r"(b1));
}
__device__ __forceinline__ void cp16(uint32_t dst, const void* src) {
    asm volatile("cp.async.cg.shared.global [%0], [%1], 16;" :: "r"(dst), "l"(src));
}
__device__ __forceinline__ void cp_commit() {
    asm volatile("cp.async.commit_group;" ::: "memory");
}
template <int N> __device__ __forceinline__ void cp_wait() {
    asm volatile("cp.async.wait_group %0;" :: "n"(N) : "memory");
}
__device__ __forceinline__ float fex2(float x) {
    float r;
    asm("ex2.approx.f32 %0, %1;" : "=f"(r) : "f"(x));
    return r;
}
__device__ __forceinline__ uint32_t pack_h(__half a, __half b) {
    __half2 t(a, b);
    return *(uint32_t*)&t;
}
// write fp32 pair as fp16
__device__ __forceinline__ void wcvt(__half* __restrict__ H, size_t o,
                                     float a, float b) {
    *(uint32_t*)(H + o) = pack_h(__float2half_rn(a), __float2half_rn(b));
}

// ---------------------------------------------------------------------------
// fp32 -> fp16 convert (vectorized x4)
// ---------------------------------------------------------------------------
__global__ __launch_bounds__(256) void cvt_kernel(const float* __restrict__ in,
                                                  __half* __restrict__ out,
                                                  int n4) {
    int i = blockIdx.x * blockDim.x + threadIdx.x;
    if (i >= n4) return;
    float4 v = ((const float4*)in)[i];
    ((__half2*)out)[i * 2 + 0] = __half2(__float2half_rn(v.x), __float2half_rn(v.y));
    ((__half2*)out)[i * 2 + 1] = __half2(__float2half_rn(v.z), __float2half_rn(v.w));
}

// ---------------------------------------------------------------------------
// Transpose + convert: fp32 [Kd, Nd] -> fp16 [Nd, Kd]
// ---------------------------------------------------------------------------
__global__ __launch_bounds__(256) void tcvt_kernel(const float* __restrict__ in,
                                                   __half* __restrict__ out,
                                                   int Kd, int Nd) {
    __shared__ float t[32][33];
    int n0 = blockIdx.x * 32, k0 = blockIdx.y * 32;
    int tx = threadIdx.x & 31, ty = threadIdx.x >> 5;
#pragma unroll
    for (int j = 0; j < 4; j++)
        t[ty + j * 8][tx] = in[(size_t)(k0 + ty + j * 8) * Nd + n0 + tx];
    __syncthreads();
#pragma unroll
    for (int j = 0; j < 4; j++)
        out[(size_t)(n0 + ty + j * 8) * Kd + k0 + tx] =
            __float2half_rn(t[tx][ty + j * 8]);
}

// ---------------------------------------------------------------------------
// fp16 single-pass GEMM: C = A @ B^T, A [M,K], B [N,K] fp16.
// 128x128 tile, 3-stage cp.async pipeline, occ 2.
// mode 0: fp32 C. mode 1: fused QKV epilogue (RoPE+scale, fp16 out).
// ---------------------------------------------------------------------------
#define GROW 40
#define GARR (128 * GROW * 2)        // 10240
#define GSTAGE_B (2 * GARR)          // 20480 (A, B)
#define GEMM_SMEM (3 * GSTAGE_B)     // 61440 -> occ 2+

#define GLOAD(kc, st)                                                        \
    do {                                                                     \
        uint32_t uS = uBase + (st) * GSTAGE_B;                               \
        int koff = (kc) * 32;                                                \
        _Pragma("unroll") for (int t = 0; t < 2; t++) {                      \
            int idx = tid + t * 256;                                         \
            int r = idx >> 2, c8 = (idx & 3) * 8;                            \
            size_t go = (size_t)r * K + koff + c8;                           \
            uint32_t dso = (uint32_t)(r * (GROW * 2) + c8 * 2);              \
            cp16(uS + dso, gA + go);                                         \
            cp16(uS + GARR + dso, gB + go);                                  \
        }                                                                    \
    } while (0)

__global__ __launch_bounds__(256, 2) void gemm_mma(
    const __half* __restrict__ A, const __half* __restrict__ B,
    float* __restrict__ Cf,
    __half* __restrict__ Qo, __half* __restrict__ Ko, __half* __restrict__ Vo,
    int mode, int M, int N, int K) {
    extern __shared__ char gsm[];
    const uint32_t uBase = smem_u32(gsm);

    const int tid = threadIdx.x, wid = tid >> 5, lane = tid & 31;
    const int m0 = blockIdx.y * 128, n0 = blockIdx.x * 128;
    const int warp_m = (wid >> 2) * 64;
    const int warp_n = (wid & 3) * 32;

    const int a_roff = ((lane >> 3) & 1) * 8 + (lane & 7);
    const int a_coff = (lane >> 4) * 8;
    const int b_roff = (lane >> 4) * 8 + (lane & 7);
    const int b_coff = ((lane >> 3) & 1) * 8;

    float acc[4][4][4];
#pragma unroll
    for (int i = 0; i < 4; i++)
#pragma unroll
        for (int j = 0; j < 4; j++)
#pragma unroll
            for (int c = 0; c < 4; c++) acc[i][j][c] = 0.f;

    const __half* gA = A + (size_t)m0 * K;
    const __half* gB = B + (size_t)n0 * K;

    const int KC = K >> 5;
    GLOAD(0, 0);
    cp_commit();
    GLOAD(1, 1);
    cp_commit();

    int st = 0, stp = 2;
    for (int kc = 0; kc < KC; kc++) {
        if (kc + 1 < KC) cp_wait<1>(); else cp_wait<0>();
        __syncthreads();
        if (kc + 2 < KC) {
            GLOAD(kc + 2, stp);
            cp_commit();
        }

        const uint32_t uS = uBase + st * GSTAGE_B;
        const uint32_t uA = uS, uB = uS + GARR;

#pragma unroll
        for (int ks = 0; ks < 2; ks++) {
            uint32_t ah[4][4];
#pragma unroll
            for (int mt = 0; mt < 4; mt++) {
                uint32_t off =
                    (uint32_t)((warp_m + mt * 16 + a_roff) * GROW +
                               ks * 16 + a_coff) * 2;
                ldsm_x4(ah[mt], uA + off);
            }
#pragma unroll
            for (int p = 0; p < 2; p++) {
                uint32_t bf[4];
                uint32_t off =
                    (uint32_t)((warp_n + p * 16 + b_roff) * GROW +
                               ks * 16 + b_coff) * 2;
                ldsm_x4(bf, uB + off);
#pragma unroll
                for (int mt = 0; mt < 4; mt++) {
#pragma unroll
                    for (int hf = 0; hf < 2; hf++)
                        mma16816h(acc[mt][p * 2 + hf], ah[mt],
                                  bf[hf * 2], bf[hf * 2 + 1]);
                }
            }
        }
        st = (st == 2) ? 0 : st + 1;
        stp = (stp == 2) ? 0 : stp + 1;
    }

    const int cr = lane >> 2, cc = (lane & 3) * 2;
    if (mode == 0) {
#pragma unroll
        for (int mt = 0; mt < 4; mt++) {
#pragma unroll
            for (int nt = 0; nt < 4; nt++) {
                int row = m0 + warp_m + mt * 16 + cr;
                int col = n0 + warp_n + nt * 8 + cc;
                float* c = acc[mt][nt];
                *(float2*)(Cf + (size_t)row * N + col) = make_float2(c[0], c[1]);
                *(float2*)(Cf + (size_t)(row + 8) * N + col) =
                    make_float2(c[2], c[3]);
            }
        }
    } else {
        // QKV fused epilogue: col pair (col, col+1) is a RoPE rotation pair.
        // Q folds log2(e) so flash softmax uses raw ex2.
        const float qscale = 0.12751742f;  // log2(e)/sqrt(HD)
#pragma unroll
        for (int mt = 0; mt < 4; mt++) {
#pragma unroll
            for (int nt = 0; nt < 4; nt++) {
                int row = m0 + warp_m + mt * 16 + cr;
                int col = n0 + warp_n + nt * 8 + cc;
                float* c = acc[mt][nt];
                int s0 = row & (SS - 1);
                if (col < EE) {
                    int i = (col & (HD - 1)) >> 1;
                    float f = exp2f(-(float)i * (13.287712379549449f / 64.0f));
                    float sn0, cs0, sn1, cs1;
                    sincosf((float)s0 * f, &sn0, &cs0);
                    sincosf((float)(s0 + 8) * f, &sn1, &cs1);
                    wcvt(Qo, (size_t)row * EE + col,
                         (c[0] * cs0 - c[1] * sn0) * qscale,
                         (c[0] * sn0 + c[1] * cs0) * qscale);
                    wcvt(Qo, (size_t)(row + 8) * EE + col,
                         (c[2] * cs1 - c[3] * sn1) * qscale,
                         (c[2] * sn1 + c[3] * cs1) * qscale);
                } else if (col < EE + NKV) {
                    int colk = col - EE;
                    int i = (colk & (HD - 1)) >> 1;
                    float f = exp2f(-(float)i * (13.287712379549449f / 64.0f));
                    float sn0, cs0, sn1, cs1;
                    sincosf((float)s0 * f, &sn0, &cs0);
                    sincosf((float)(s0 + 8) * f, &sn1, &cs1);
                    wcvt(Ko, (size_t)row * NKV + colk,
                         c[0] * cs0 - c[1] * sn0, c[0] * sn0 + c[1] * cs0);
                    wcvt(Ko, (size_t)(row + 8) * NKV + colk,
                         c[2] * cs1 - c[3] * sn1, c[2] * sn1 + c[3] * cs1);
                } else {
                    int colv = col - EE - NKV;
                    wcvt(Vo, (size_t)row * NKV + colv, c[0], c[1]);
                    wcvt(Vo, (size_t)(row + 8) * NKV + colv, c[2], c[3]);
                }
            }
        }
    }
}

// ---------------------------------------------------------------------------
// Flash attention, all-fp16 MMA (fp32 accum). BQ=128 (8 warps x 16 rows),
// BK=64, HD=128. Scores pre-scaled by log2(e). occ 2.
// ---------------------------------------------------------------------------
#define FROW 136
#define FQ_B (128 * FROW * 2)        // 34816
#define FKV_B (64 * FROW * 2)        // 17408
#define FSTAGE_B (2 * FKV_B)         // 34816
#define FLA_SMEM (FQ_B + 2 * FSTAGE_B)   // 104448

#define KVLOAD(j, st)                                                         \
    do {                                                                      \
        uint32_t uS = uBase + FQ_B + (st) * FSTAGE_B;                         \
        _Pragma("unroll") for (int t = 0; t < 4; t++) {                       \
            int i = tid + t * 256;                                            \
            int r = i >> 4, c8 = (i & 15) << 3;                               \
            size_t g = (size_t)(b * SS + (j) * 64 + r) * NKV + kvh * HD + c8; \
            uint32_t dso = (uint32_t)(r * (FROW * 2) + c8 * 2);               \
            cp16(uS + dso, Kk + g);                                           \
            cp16(uS + FKV_B + dso, Vv + g);                                   \
        }                                                                     \
    } while (0)

__global__ __launch_bounds__(256, 2) void flash_mma(
    const __half* __restrict__ Q,
    const __half* __restrict__ Kk, const __half* __restrict__ Vv,
    __half* __restrict__ O) {
    extern __shared__ char fsm[];
    const uint32_t uBase = smem_u32(fsm);
    const uint32_t uQ = uBase;

    const int qt = gridDim.x - 1 - blockIdx.x;   // heavy tiles first
    const int h = blockIdx.y, b = blockIdx.z;
    const int kvh = h >> 2;
    const int tid = threadIdx.x, wid = tid >> 5, lane = tid & 31;
    const int cr = lane >> 2, tc = (lane & 3) << 1;

    const int a_roff = ((lane >> 3) & 1) * 8 + (lane & 7);
    const int a_coff = (lane >> 4) * 8;
    const int b_roff = (lane >> 4) * 8 + (lane & 7);
    const int b_coff = ((lane >> 3) & 1) * 8;
    const int v_roff = ((lane >> 3) & 1) * 8 + (lane & 7);
    const int v_coff = (lane >> 4) * 8;

    {
        const size_t qbase = (size_t)(b * SS + qt * 128) * EE + h * HD;
#pragma unroll
        for (int t = 0; t < 8; t++) {
            int i = tid + t * 256;
            int r = i >> 4, c8 = (i & 15) << 3;
            cp16(uQ + (uint32_t)(r * (FROW * 2) + c8 * 2),
                 Q + qbase + (size_t)r * EE + c8);
        }
        cp_commit();
    }
    KVLOAD(0, 0);
    cp_commit();

    float oacc[16][4];
#pragma unroll
    for (int i = 0; i < 16; i++)
#pragma unroll
        for (int c = 0; c < 4; c++) oacc[i][c] = 0.f;
    float m0 = -1e30f, m1 = -1e30f, l0 = 0.f, l1 = 0.f;

    const int border = qt * 128 + wid * 16;
    const int jmax = 2 * qt + 1;

    for (int j = 0; j <= jmax; j++) {
        if (j + 1 <= jmax) {
            KVLOAD(j + 1, (j + 1) & 1);
            cp_commit();
            cp_wait<1>();
        } else {
            cp_wait<0>();
        }
        __syncthreads();

        const uint32_t uS = uBase + FQ_B + (j & 1) * FSTAGE_B;
        const uint32_t uK = uS, uV = uS + FKV_B;

        if (j * 64 <= border + 15) {
            // ---- Scores S = Q @ K^T ----
            float sacc[8][4];
#pragma unroll
            for (int nt = 0; nt < 8; nt++)
#pragma unroll
                for (int c = 0; c < 4; c++) sacc[nt][c] = 0.f;

#pragma unroll
            for (int ks = 0; ks < 8; ks++) {
                uint32_t qf[4];
                ldsm_x4(qf, uQ + (uint32_t)((wid * 16 + a_roff) * FROW +
                                            ks * 16 + a_coff) * 2);
#pragma unroll
                for (int p = 0; p < 4; p++) {
                    uint32_t kf[4];
                    uint32_t off =
                        (uint32_t)((p * 16 + b_roff) * FROW +
                                   ks * 16 + b_coff) * 2;
                    ldsm_x4(kf, uK + off);
#pragma unroll
                    for (int hf = 0; hf < 2; hf++)
                        mma16816h(sacc[p * 2 + hf], qf, kf[hf * 2], kf[hf * 2 + 1]);
                }
            }

            if (j * 64 + 63 > border) {
                int qg0 = border + cr, qg1 = qg0 + 8;
#pragma unroll
                for (int nt = 0; nt < 8; nt++) {
                    int kg = j * 64 + nt * 8 + tc;
                    if (kg > qg0) sacc[nt][0] = -1e30f;
                    if (kg + 1 > qg0) sacc[nt][1] = -1e30f;
                    if (kg > qg1) sacc[nt][2] = -1e30f;
                    if (kg + 1 > qg1) sacc[nt][3] = -1e30f;
                }
            }

            float mx0 = -1e30f, mx1 = -1e30f;
#pragma unroll
            for (int nt = 0; nt < 8; nt++) {
                mx0 = fmaxf(mx0, fmaxf(sacc[nt][0], sacc[nt][1]));
                mx1 = fmaxf(mx1, fmaxf(sacc[nt][2], sacc[nt][3]));
            }
            mx0 = fmaxf(mx0, __shfl_xor_sync(0xffffffffu, mx0, 1, 4));
            mx0 = fmaxf(mx0, __shfl_xor_sync(0xffffffffu, mx0, 2, 4));
            mx1 = fmaxf(mx1, __shfl_xor_sync(0xffffffffu, mx1, 1, 4));
            mx1 = fmaxf(mx1, __shfl_xor_sync(0xffffffffu, mx1, 2, 4));
            float mn0 = fmaxf(m0, mx0), mn1 = fmaxf(m1, mx1);
            float al0 = fex2(m0 - mn0), al1 = fex2(m1 - mn1);

            float sum0 = 0.f, sum1 = 0.f;
            uint32_t ph[8][2];
#pragma unroll
            for (int nt = 0; nt < 8; nt++) {
                float p00 = fex2(sacc[nt][0] - mn0);
                float p01 = fex2(sacc[nt][1] - mn0);
                float p10 = fex2(sacc[nt][2] - mn1);
                float p11 = fex2(sacc[nt][3] - mn1);
                sum0 += p00 + p01;
                sum1 += p10 + p11;
                ph[nt][0] = pack_h(__float2half_rn(p00), __float2half_rn(p01));
                ph[nt][1] = pack_h(__float2half_rn(p10), __float2half_rn(p11));
            }
            sum0 += __shfl_xor_sync(0xffffffffu, sum0, 1, 4);
            sum0 += __shfl_xor_sync(0xffffffffu, sum0, 2, 4);
            sum1 += __shfl_xor_sync(0xffffffffu, sum1, 1, 4);
            sum1 += __shfl_xor_sync(0xffffffffu, sum1, 2, 4);
            l0 = l0 * al0 + sum0;
            l1 = l1 * al1 + sum1;
            m0 = mn0;
            m1 = mn1;
#pragma unroll
            for (int nt = 0; nt < 16; nt++) {
                oacc[nt][0] *= al0;
                oacc[nt][1] *= al0;
                oacc[nt][2] *= al1;
                oacc[nt][3] *= al1;
            }

            // ---- O += P @ V ----
#pragma unroll
            for (int ks = 0; ks < 4; ks++) {
                uint32_t ah4[4] = {ph[2 * ks][0], ph[2 * ks][1],
                                   ph[2 * ks + 1][0], ph[2 * ks + 1][1]};
#pragma unroll
                for (int p = 0; p < 8; p++) {
                    uint32_t vf[4];
                    uint32_t off =
                        (uint32_t)((ks * 16 + v_roff) * FROW +
                                   p * 16 + v_coff) * 2;
                    ldsm_x4_t(vf, uV + off);
#pragma unroll
                    for (int hf = 0; hf < 2; hf++)
                        mma16816h(oacc[p * 2 + hf], ah4, vf[hf * 2], vf[hf * 2 + 1]);
                }
            }
        }
        __syncthreads();
    }

    // ---- Epilogue: normalize + fp16 context ----
    float inv0 = 1.0f / l0, inv1 = 1.0f / l1;
    int row0 = qt * 128 + wid * 16 + cr;
    size_t obase = (size_t)(b * SS + row0) * EE + h * HD;
#pragma unroll
    for (int nt = 0; nt < 16; nt++) {
        int col = nt * 8 + tc;
        wcvt(O, obase + col, oacc[nt][0] * inv0, oacc[nt][1] * inv0);
        wcvt(O, obase + (size_t)8 * EE + col,
             oacc[nt][2] * inv1, oacc[nt][3] * inv1);
    }
}

// ---------------------------------------------------------------------------
// Launch
// ---------------------------------------------------------------------------
extern "C" void kernel_launch(void* const* d_in, const int* in_sizes, int n_in,
                              void* d_out, int out_size) {
    const float* x  = (const float*)d_in[0];
    const float* Wq = (const float*)d_in[1];
    const float* Wk = (const float*)d_in[2];
    const float* Wv = (const float*)d_in[3];
    const float* Wo = (const float*)d_in[4];

    __half *X, *Qb, *Kb, *Vb, *CX, *Wc, *Wob;
    cudaGetSymbolAddress((void**)&X, g_X);
    cudaGetSymbolAddress((void**)&Qb, g_Qb);
    cudaGetSymbolAddress((void**)&Kb, g_Kb);
    cudaGetSymbolAddress((void**)&Vb, g_Vb);
    cudaGetSymbolAddress((void**)&CX, g_CX);
    cudaGetSymbolAddress((void**)&Wc, g_Wc);
    cudaGetSymbolAddress((void**)&Wob, g_Wo);

    cudaFuncSetAttribute(gemm_mma, cudaFuncAttributeMaxDynamicSharedMemorySize,
                         GEMM_SMEM);
    cudaFuncSetAttribute(flash_mma, cudaFuncAttributeMaxDynamicSharedMemorySize,
                         FLA_SMEM);

    // Convert x; transpose+convert weights (QKV concat + Wo), all fp16
    cvt_kernel<<<(ROWS * EE / 4 + 255) / 256, 256>>>(x, X, ROWS * EE / 4);
    tcvt_kernel<<<dim3(EE / 32, EE / 32), 256>>>(Wq, Wc, EE, EE);
    tcvt_kernel<<<dim3(NKV / 32, EE / 32), 256>>>(
        Wk, Wc + (size_t)EE * EE, EE, NKV);
    tcvt_kernel<<<dim3(NKV / 32, EE / 32), 256>>>(
        Wv, Wc + (size_t)(EE + NKV) * EE, EE, NKV);
    tcvt_kernel<<<dim3(EE / 32, EE / 32), 256>>>(Wo, Wob, EE, EE);

    // Fused QKV projection with RoPE+scale(+log2e) epilogue (fp16 out)
    gemm_mma<<<dim3(NC / 128, ROWS / 128), 256, GEMM_SMEM>>>(
        X, Wc, nullptr, Qb, Kb, Vb, 1, ROWS, NC, EE);

    // Flash attention (fp16 MMA, fp32 accum), occ 2
    flash_mma<<<dim3(SS / 128, HH, BB), 256, FLA_SMEM>>>(Qb, Kb, Vb, CX);

    // Output projection -> d_out (fp32)
    gemm_mma<<<dim3(EE / 128, ROWS / 128), 256, GEMM_SMEM>>>(
        CX, Wob, (float*)d_out, nullptr, nullptr, nullptr,
        0, ROWS, EE, EE);
}

// round 13
// speedup vs baseline: 2.8760x; 1.0858x over previous
#include <cuda_runtime.h>
#include <cuda_fp16.h>
#include <math.h>
#include <stdint.h>

// Problem dims
#define BB 2
#define SS 2048
#define EE 2048
#define HH 16
#define KVH 4
#define HD 128
#define ROWS (BB * SS)    // 4096
#define NKV (KVH * HD)    // 512
#define NC (EE + 2 * NKV) // 3072

// ---------------------------------------------------------------------------
// Scratch (__device__ globals; no cudaMalloc allowed)
// ---------------------------------------------------------------------------
__device__ __half g_X[(size_t)ROWS * EE];        // x, fp16
__device__ __half g_Qb[(size_t)ROWS * EE];       // Q (rope+scale), fp16
__device__ __half g_Kb[(size_t)ROWS * NKV];      // K (rope), fp16
__device__ __half g_Vb[(size_t)ROWS * NKV];      // V, fp16
__device__ __half g_CX[(size_t)ROWS * EE];       // context, fp16
__device__ __half g_Wc[(size_t)NC * EE];         // QKV weights concat [N,K]
__device__ __half g_Wo[(size_t)EE * EE];         // Wo [N,K]

// ---------------------------------------------------------------------------
// MMA / cp.async helpers
// ---------------------------------------------------------------------------
__device__ __forceinline__ uint32_t smem_u32(const void* p) {
    uint32_t a;
    asm("{ .reg .u64 t; cvta.to.shared.u64 t, %1; cvt.u32.u64 %0, t; }"
        : "=r"(a) : "l"(p));
    return a;
}
__device__ __forceinline__ void ldsm_x4(uint32_t* r, uint32_t addr) {
    asm volatile("ldmatrix.sync.aligned.m8n8.x4.shared.b16 {%0,%1,%2,%3}, [%4];"
                 : "=r"(r[0]), "=r"(r[1]), "=r"(r[2]), "=r"(r[3]) : "r"(addr));
}
__device__ __forceinline__ void ldsm_x4_t(uint32_t* r, uint32_t addr) {
    asm volatile("ldmatrix.sync.aligned.m8n8.x4.trans.shared.b16 {%0,%1,%2,%3}, [%4];"
                 : "=r"(r[0]), "=r"(r[1]), "=r"(r[2]), "=r"(r[3]) : "r"(addr));
}
// fp16 HMMA m16n8k16, fp32 accumulate
__device__ __forceinline__ void mma16816h(float* c, const uint32_t* a,
                                          uint32_t b0, uint32_t b1) {
    asm volatile(
        "mma.sync.aligned.m16n8k16.row.col.f32.f16.f16.f32 "
        "{%0,%1,%2,%3}, {%4,%5,%6,%7}, {%8,%9}, {%0,%1,%2,%3};"
        : "+f"(c[0]), "+f"(c[1]), "+f"(c[2]), "+f"(c[3])
        : "r"(a[0]), "r"(a[1]), "r"(a[2]), "r"(a[3]), "r"(b0), "r"(b1));
}
__device__ __forceinline__ void cp16(uint32_t dst, const void* src) {
    asm volatile("cp.async.cg.shared.global [%0], [%1], 16;" :: "r"(dst), "l"(src));
}
__device__ __forceinline__ void cp_commit() {
    asm volatile("cp.async.commit_group;" ::: "memory");
}
template <int N> __device__ __forceinline__ void cp_wait() {
    asm volatile("cp.async.wait_group %0;" :: "n"(N) : "memory");
}
__device__ __forceinline__ float fex2(float x) {
    float r;
    asm("ex2.approx.f32 %0, %1;" : "=f"(r) : "f"(x));
    return r;
}
__device__ __forceinline__ uint32_t pack_h(__half a, __half b) {
    __half2 t(a, b);
    return *(uint32_t*)&t;
}
// write fp32 pair as fp16
__device__ __forceinline__ void wcvt(__half* __restrict__ H, size_t o,
                                     float a, float b) {
    *(uint32_t*)(H + o) = pack_h(__float2half_rn(a), __float2half_rn(b));
}

// ---------------------------------------------------------------------------
// fp32 -> fp16 convert (vectorized x4)
// ---------------------------------------------------------------------------
__global__ __launch_bounds__(256) void cvt_kernel(const float* __restrict__ in,
                                                  __half* __restrict__ out,
                                                  int n4) {
    int i = blockIdx.x * blockDim.x + threadIdx.x;
    if (i >= n4) return;
    float4 v = ((const float4*)in)[i];
    ((__half2*)out)[i * 2 + 0] = __half2(__float2half_rn(v.x), __float2half_rn(v.y));
    ((__half2*)out)[i * 2 + 1] = __half2(__float2half_rn(v.z), __float2half_rn(v.w));
}

// ---------------------------------------------------------------------------
// Transpose + convert: fp32 [Kd, Nd] -> fp16 [Nd, Kd]
// ---------------------------------------------------------------------------
__global__ __launch_bounds__(256) void tcvt_kernel(const float* __restrict__ in,
                                                   __half* __restrict__ out,
                                                   int Kd, int Nd) {
    __shared__ float t[32][33];
    int n0 = blockIdx.x * 32, k0 = blockIdx.y * 32;
    int tx = threadIdx.x & 31, ty = threadIdx.x >> 5;
#pragma unroll
    for (int j = 0; j < 4; j++)
        t[ty + j * 8][tx] = in[(size_t)(k0 + ty + j * 8) * Nd + n0 + tx];
    __syncthreads();
#pragma unroll
    for (int j = 0; j < 4; j++)
        out[(size_t)(n0 + ty + j * 8) * Kd + k0 + tx] =
            __float2half_rn(t[tx][ty + j * 8]);
}

// ---------------------------------------------------------------------------
// fp16 single-pass GEMM: C = A @ B^T, A [M,K], B [N,K] fp16.
// 128x128 tile, K-tile 64, 3-stage cp.async pipeline, occ 2.
// mode 0: fp32 C. mode 1: fused QKV epilogue (RoPE+scale, fp16 out).
// ---------------------------------------------------------------------------
#define GROW 72                      // 64 + 8 pad, halves per smem row
#define GARR (128 * GROW * 2)        // 18432
#define GSTAGE_B (2 * GARR)          // 36864 (A, B)
#define GEMM_SMEM (3 * GSTAGE_B)     // 110592 -> occ 2

#define GLOAD(kc, st)                                                        \
    do {                                                                     \
        uint32_t uS = uBase + (st) * GSTAGE_B;                               \
        int koff = (kc) * 64;                                                \
        _Pragma("unroll") for (int t = 0; t < 4; t++) {                      \
            int idx = tid + t * 256;                                         \
            int r = idx >> 3, c8 = (idx & 7) * 8;                            \
            size_t go = (size_t)r * K + koff + c8;                           \
            uint32_t dso = (uint32_t)(r * (GROW * 2) + c8 * 2);              \
            cp16(uS + dso, gA + go);                                         \
            cp16(uS + GARR + dso, gB + go);                                  \
        }                                                                    \
    } while (0)

__global__ __launch_bounds__(256, 2) void gemm_mma(
    const __half* __restrict__ A, const __half* __restrict__ B,
    float* __restrict__ Cf,
    __half* __restrict__ Qo, __half* __restrict__ Ko, __half* __restrict__ Vo,
    int mode, int M, int N, int K) {
    extern __shared__ char gsm[];
    const uint32_t uBase = smem_u32(gsm);

    const int tid = threadIdx.x, wid = tid >> 5, lane = tid & 31;
    const int m0 = blockIdx.y * 128, n0 = blockIdx.x * 128;
    const int warp_m = (wid >> 2) * 64;
    const int warp_n = (wid & 3) * 32;

    const int a_roff = ((lane >> 3) & 1) * 8 + (lane & 7);
    const int a_coff = (lane >> 4) * 8;
    const int b_roff = (lane >> 4) * 8 + (lane & 7);
    const int b_coff = ((lane >> 3) & 1) * 8;

    float acc[4][4][4];
#pragma unroll
    for (int i = 0; i < 4; i++)
#pragma unroll
        for (int j = 0; j < 4; j++)
#pragma unroll
            for (int c = 0; c < 4; c++) acc[i][j][c] = 0.f;

    const __half* gA = A + (size_t)m0 * K;
    const __half* gB = B + (size_t)n0 * K;

    const int KC = K >> 6;
    GLOAD(0, 0);
    cp_commit();
    GLOAD(1, 1);
    cp_commit();

    int st = 0, stp = 2;
    for (int kc = 0; kc < KC; kc++) {
        if (kc + 1 < KC) cp_wait<1>(); else cp_wait<0>();
        __syncthreads();
        if (kc + 2 < KC) {
            GLOAD(kc + 2, stp);
            cp_commit();
        }

        const uint32_t uS = uBase + st * GSTAGE_B;
        const uint32_t uA = uS, uB = uS + GARR;

#pragma unroll
        for (int ks = 0; ks < 4; ks++) {
            uint32_t ah[4][4];
#pragma unroll
            for (int mt = 0; mt < 4; mt++) {
                uint32_t off =
                    (uint32_t)((warp_m + mt * 16 + a_roff) * GROW +
                               ks * 16 + a_coff) * 2;
                ldsm_x4(ah[mt], uA + off);
            }
#pragma unroll
            for (int p = 0; p < 2; p++) {
                uint32_t bf[4];
                uint32_t off =
                    (uint32_t)((warp_n + p * 16 + b_roff) * GROW +
                               ks * 16 + b_coff) * 2;
                ldsm_x4(bf, uB + off);
#pragma unroll
                for (int mt = 0; mt < 4; mt++) {
#pragma unroll
                    for (int hf = 0; hf < 2; hf++)
                        mma16816h(acc[mt][p * 2 + hf], ah[mt],
                                  bf[hf * 2], bf[hf * 2 + 1]);
                }
            }
        }
        st = (st == 2) ? 0 : st + 1;
        stp = (stp == 2) ? 0 : stp + 1;
    }

    const int cr = lane >> 2, cc = (lane & 3) * 2;
    if (mode == 0) {
#pragma unroll
        for (int mt = 0; mt < 4; mt++) {
#pragma unroll
            for (int nt = 0; nt < 4; nt++) {
                int row = m0 + warp_m + mt * 16 + cr;
                int col = n0 + warp_n + nt * 8 + cc;
                float* c = acc[mt][nt];
                *(float2*)(Cf + (size_t)row * N + col) = make_float2(c[0], c[1]);
                *(float2*)(Cf + (size_t)(row + 8) * N + col) =
                    make_float2(c[2], c[3]);
            }
        }
    } else {
        // QKV fused epilogue: col pair (col, col+1) is a RoPE rotation pair.
        // Q folds log2(e) so flash softmax uses raw ex2.
        const float qscale = 0.12751742f;  // log2(e)/sqrt(HD)
#pragma unroll
        for (int mt = 0; mt < 4; mt++) {
#pragma unroll
            for (int nt = 0; nt < 4; nt++) {
                int row = m0 + warp_m + mt * 16 + cr;
                int col = n0 + warp_n + nt * 8 + cc;
                float* c = acc[mt][nt];
                int s0 = row & (SS - 1);
                if (col < EE) {
                    int i = (col & (HD - 1)) >> 1;
                    float f = exp2f(-(float)i * (13.287712379549449f / 64.0f));
                    float sn0, cs0, sn1, cs1;
                    sincosf((float)s0 * f, &sn0, &cs0);
                    sincosf((float)(s0 + 8) * f, &sn1, &cs1);
                    wcvt(Qo, (size_t)row * EE + col,
                         (c[0] * cs0 - c[1] * sn0) * qscale,
                         (c[0] * sn0 + c[1] * cs0) * qscale);
                    wcvt(Qo, (size_t)(row + 8) * EE + col,
                         (c[2] * cs1 - c[3] * sn1) * qscale,
                         (c[2] * sn1 + c[3] * cs1) * qscale);
                } else if (col < EE + NKV) {
                    int colk = col - EE;
                    int i = (colk & (HD - 1)) >> 1;
                    float f = exp2f(-(float)i * (13.287712379549449f / 64.0f));
                    float sn0, cs0, sn1, cs1;
                    sincosf((float)s0 * f, &sn0, &cs0);
                    sincosf((float)(s0 + 8) * f, &sn1, &cs1);
                    wcvt(Ko, (size_t)row * NKV + colk,
                         c[0] * cs0 - c[1] * sn0, c[0] * sn0 + c[1] * cs0);
                    wcvt(Ko, (size_t)(row + 8) * NKV + colk,
                         c[2] * cs1 - c[3] * sn1, c[2] * sn1 + c[3] * cs1);
                } else {
                    int colv = col - EE - NKV;
                    wcvt(Vo, (size_t)row * NKV + colv, c[0], c[1]);
                    wcvt(Vo, (size_t)(row + 8) * NKV + colv, c[2], c[3]);
                }
            }
        }
    }
}

// ---------------------------------------------------------------------------
// Flash attention, all-fp16 MMA (fp32 accum). BQ=128 (8 warps x 16 rows),
// BK=64, HD=128. Scores pre-scaled by log2(e). occ 2.
// Rescale of O accumulators skipped warp-uniformly when alpha==1 exactly.
// ---------------------------------------------------------------------------
#define FROW 136
#define FQ_B (128 * FROW * 2)        // 34816
#define FKV_B (64 * FROW * 2)        // 17408
#define FSTAGE_B (2 * FKV_B)         // 34816
#define FLA_SMEM (FQ_B + 2 * FSTAGE_B)   // 104448

#define KVLOAD(j, st)                                                         \
    do {                                                                      \
        uint32_t uS = uBase + FQ_B + (st) * FSTAGE_B;                         \
        _Pragma("unroll") for (int t = 0; t < 4; t++) {                       \
            int i = tid + t * 256;                                            \
            int r = i >> 4, c8 = (i & 15) << 3;                               \
            size_t g = (size_t)(b * SS + (j) * 64 + r) * NKV + kvh * HD + c8; \
            uint32_t dso = (uint32_t)(r * (FROW * 2) + c8 * 2);               \
            cp16(uS + dso, Kk + g);                                           \
            cp16(uS + FKV_B + dso, Vv + g);                                   \
        }                                                                     \
    } while (0)

__global__ __launch_bounds__(256, 2) void flash_mma(
    const __half* __restrict__ Q,
    const __half* __restrict__ Kk, const __half* __restrict__ Vv,
    __half* __restrict__ O) {
    extern __shared__ char fsm[];
    const uint32_t uBase = smem_u32(fsm);
    const uint32_t uQ = uBase;

    const int qt = gridDim.x - 1 - blockIdx.x;   // heavy tiles first
    const int h = blockIdx.y, b = blockIdx.z;
    const int kvh = h >> 2;
    const int tid = threadIdx.x, wid = tid >> 5, lane = tid & 31;
    const int cr = lane >> 2, tc = (lane & 3) << 1;

    const int a_roff = ((lane >> 3) & 1) * 8 + (lane & 7);
    const int a_coff = (lane >> 4) * 8;
    const int b_roff = (lane >> 4) * 8 + (lane & 7);
    const int b_coff = ((lane >> 3) & 1) * 8;
    const int v_roff = ((lane >> 3) & 1) * 8 + (lane & 7);
    const int v_coff = (lane >> 4) * 8;

    {
        const size_t qbase = (size_t)(b * SS + qt * 128) * EE + h * HD;
#pragma unroll
        for (int t = 0; t < 8; t++) {
            int i = tid + t * 256;
            int r = i >> 4, c8 = (i & 15) << 3;
            cp16(uQ + (uint32_t)(r * (FROW * 2) + c8 * 2),
                 Q + qbase + (size_t)r * EE + c8);
        }
        cp_commit();
    }
    KVLOAD(0, 0);
    cp_commit();

    float oacc[16][4];
#pragma unroll
    for (int i = 0; i < 16; i++)
#pragma unroll
        for (int c = 0; c < 4; c++) oacc[i][c] = 0.f;
    float m0 = -1e30f, m1 = -1e30f, l0 = 0.f, l1 = 0.f;

    const int border = qt * 128 + wid * 16;
    const int jmax = 2 * qt + 1;

    for (int j = 0; j <= jmax; j++) {
        if (j + 1 <= jmax) {
            KVLOAD(j + 1, (j + 1) & 1);
            cp_commit();
            cp_wait<1>();
        } else {
            cp_wait<0>();
        }
        __syncthreads();

        const uint32_t uS = uBase + FQ_B + (j & 1) * FSTAGE_B;
        const uint32_t uK = uS, uV = uS + FKV_B;

        if (j * 64 <= border + 15) {
            // ---- Scores S = Q @ K^T ----
            float sacc[8][4];
#pragma unroll
            for (int nt = 0; nt < 8; nt++)
#pragma unroll
                for (int c = 0; c < 4; c++) sacc[nt][c] = 0.f;

#pragma unroll
            for (int ks = 0; ks < 8; ks++) {
                uint32_t qf[4];
                ldsm_x4(qf, uQ + (uint32_t)((wid * 16 + a_roff) * FROW +
                                            ks * 16 + a_coff) * 2);
#pragma unroll
                for (int p = 0; p < 4; p++) {
                    uint32_t kf[4];
                    uint32_t off =
                        (uint32_t)((p * 16 + b_roff) * FROW +
                                   ks * 16 + b_coff) * 2;
                    ldsm_x4(kf, uK + off);
#pragma unroll
                    for (int hf = 0; hf < 2; hf++)
                        mma16816h(sacc[p * 2 + hf], qf, kf[hf * 2], kf[hf * 2 + 1]);
                }
            }

            if (j * 64 + 63 > border) {
                int qg0 = border + cr, qg1 = qg0 + 8;
#pragma unroll
                for (int nt = 0; nt < 8; nt++) {
                    int kg = j * 64 + nt * 8 + tc;
                    if (kg > qg0) sacc[nt][0] = -1e30f;
                    if (kg + 1 > qg0) sacc[nt][1] = -1e30f;
                    if (kg > qg1) sacc[nt][2] = -1e30f;
                    if (kg + 1 > qg1) sacc[nt][3] = -1e30f;
                }
            }

            float mx0 = -1e30f, mx1 = -1e30f;
#pragma unroll
            for (int nt = 0; nt < 8; nt++) {
                mx0 = fmaxf(mx0, fmaxf(sacc[nt][0], sacc[nt][1]));
                mx1 = fmaxf(mx1, fmaxf(sacc[nt][2], sacc[nt][3]));
            }
            mx0 = fmaxf(mx0, __shfl_xor_sync(0xffffffffu, mx0, 1, 4));
            mx0 = fmaxf(mx0, __shfl_xor_sync(0xffffffffu, mx0, 2, 4));
            mx1 = fmaxf(mx1, __shfl_xor_sync(0xffffffffu, mx1, 1, 4));
            mx1 = fmaxf(mx1, __shfl_xor_sync(0xffffffffu, mx1, 2, 4));
            float mn0 = fmaxf(m0, mx0), mn1 = fmaxf(m1, mx1);
            // alpha == 1 exactly when the max did not move
            bool noresc = (mn0 == m0) && (mn1 == m1);
            float al0 = noresc ? 1.f : fex2(m0 - mn0);
            float al1 = noresc ? 1.f : fex2(m1 - mn1);

            float sum0 = 0.f, sum1 = 0.f;
            uint32_t ph[8][2];
#pragma unroll
            for (int nt = 0; nt < 8; nt++) {
                float p00 = fex2(sacc[nt][0] - mn0);
                float p01 = fex2(sacc[nt][1] - mn0);
                float p10 = fex2(sacc[nt][2] - mn1);
                float p11 = fex2(sacc[nt][3] - mn1);
                sum0 += p00 + p01;
                sum1 += p10 + p11;
                ph[nt][0] = pack_h(__float2half_rn(p00), __float2half_rn(p01));
                ph[nt][1] = pack_h(__float2half_rn(p10), __float2half_rn(p11));
            }
            sum0 += __shfl_xor_sync(0xffffffffu, sum0, 1, 4);
            sum0 += __shfl_xor_sync(0xffffffffu, sum0, 2, 4);
            sum1 += __shfl_xor_sync(0xffffffffu, sum1, 1, 4);
            sum1 += __shfl_xor_sync(0xffffffffu, sum1, 2, 4);
            l0 = l0 * al0 + sum0;
            l1 = l1 * al1 + sum1;
            m0 = mn0;
            m1 = mn1;
            // warp-uniform skip of the O rescale when every lane has alpha==1
            if (!__all_sync(0xffffffffu, noresc)) {
#pragma unroll
                for (int nt = 0; nt < 16; nt++) {
                    oacc[nt][0] *= al0;
                    oacc[nt][1] *= al0;
                    oacc[nt][2] *= al1;
                    oacc[nt][3] *= al1;
                }
            }

            // ---- O += P @ V ----
#pragma unroll
            for (int ks = 0; ks < 4; ks++) {
                uint32_t ah4[4] = {ph[2 * ks][0], ph[2 * ks][1],
                                   ph[2 * ks + 1][0], ph[2 * ks + 1][1]};
#pragma unroll
                for (int p = 0; p < 8; p++) {
                    uint32_t vf[4];
                    uint32_t off =
                        (uint32_t)((ks * 16 + v_roff) * FROW +
                                   p * 16 + v_coff) * 2;
                    ldsm_x4_t(vf, uV + off);
#pragma unroll
                    for (int hf = 0; hf < 2; hf++)
                        mma16816h(oacc[p * 2 + hf], ah4, vf[hf * 2], vf[hf * 2 + 1]);
                }
            }
        }
        __syncthreads();
    }

    // ---- Epilogue: normalize + fp16 context ----
    float inv0 = 1.0f / l0, inv1 = 1.0f / l1;
    int row0 = qt * 128 + wid * 16 + cr;
    size_t obase = (size_t)(b * SS + row0) * EE + h * HD;
#pragma unroll
    for (int nt = 0; nt < 16; nt++) {
        int col = nt * 8 + tc;
        wcvt(O, obase + col, oacc[nt][0] * inv0, oacc[nt][1] * inv0);
        wcvt(O, obase + (size_t)8 * EE + col,
             oacc[nt][2] * inv1, oacc[nt][3] * inv1);
    }
}

// ---------------------------------------------------------------------------
// Launch
// ---------------------------------------------------------------------------
extern "C" void kernel_launch(void* const* d_in, const int* in_sizes, int n_in,
                              void* d_out, int out_size) {
    const float* x  = (const float*)d_in[0];
    const float* Wq = (const float*)d_in[1];
    const float* Wk = (const float*)d_in[2];
    const float* Wv = (const float*)d_in[3];
    const float* Wo = (const float*)d_in[4];

    __half *X, *Qb, *Kb, *Vb, *CX, *Wc, *Wob;
    cudaGetSymbolAddress((void**)&X, g_X);
    cudaGetSymbolAddress((void**)&Qb, g_Qb);
    cudaGetSymbolAddress((void**)&Kb, g_Kb);
    cudaGetSymbolAddress((void**)&Vb, g_Vb);
    cudaGetSymbolAddress((void**)&CX, g_CX);
    cudaGetSymbolAddress((void**)&Wc, g_Wc);
    cudaGetSymbolAddress((void**)&Wob, g_Wo);

    cudaFuncSetAttribute(gemm_mma, cudaFuncAttributeMaxDynamicSharedMemorySize,
                         GEMM_SMEM);
    cudaFuncSetAttribute(flash_mma, cudaFuncAttributeMaxDynamicSharedMemorySize,
                         FLA_SMEM);

    // Convert x; transpose+convert weights (QKV concat + Wo), all fp16
    cvt_kernel<<<(ROWS * EE / 4 + 255) / 256, 256>>>(x, X, ROWS * EE / 4);
    tcvt_kernel<<<dim3(EE / 32, EE / 32), 256>>>(Wq, Wc, EE, EE);
    tcvt_kernel<<<dim3(NKV / 32, EE / 32), 256>>>(
        Wk, Wc + (size_t)EE * EE, EE, NKV);
    tcvt_kernel<<<dim3(NKV / 32, EE / 32), 256>>>(
        Wv, Wc + (size_t)(EE + NKV) * EE, EE, NKV);
    tcvt_kernel<<<dim3(EE / 32, EE / 32), 256>>>(Wo, Wob, EE, EE);

    // Fused QKV projection with RoPE+scale(+log2e) epilogue (fp16 out)
    gemm_mma<<<dim3(NC / 128, ROWS / 128), 256, GEMM_SMEM>>>(
        X, Wc, nullptr, Qb, Kb, Vb, 1, ROWS, NC, EE);

    // Flash attention (fp16 MMA, fp32 accum), occ 2
    flash_mma<<<dim3(SS / 128, HH, BB), 256, FLA_SMEM>>>(Qb, Kb, Vb, CX);

    // Output projection -> d_out (fp32)
    gemm_mma<<<dim3(EE / 128, ROWS / 128), 256, GEMM_SMEM>>>(
        CX, Wob, (float*)d_out, nullptr, nullptr, nullptr,
        0, ROWS, EE, EE);
}